// round 9
// baseline (speedup 1.0000x reference)
#include <cuda_runtime.h>
#include <cstdint>

#define NT 2048
#define CD 768
#define INFF  __int_as_float(0x7f800000)
#define NINFF __int_as_float(0xff800000)

// ---------------------------------------------------------------------------
__device__ float g_z1n[4 * NT * CD];
__device__ float g_z2n[4 * NT * CD];
__device__ float g_sq[2 * 4 * NT];
__device__ float g_inv[2 * 4 * NT];
__device__ float g_S[NT * NT];
__device__ int   g_neighCB[NT * 5];
__device__ int   g_negCB[NT * 5];
__device__ int   g_neighA[8 * NT * 5];
__device__ int   g_bofa[NT];
__device__ int   g_aofb[NT];
__device__ int   g_idxB[NT];
__device__ int   g_order[NT];
__device__ int   g_negc;
__device__ float g_rowbuf[NT];
__device__ float g_cntbuf[NT];
__device__ float g_slots[32];

// ---------------------------------------------------------------------------
__host__ __device__ __forceinline__ void threefry2x32(
    uint32_t k0, uint32_t k1, uint32_t c0, uint32_t c1, uint32_t& o0, uint32_t& o1)
{
    uint32_t ks2 = k0 ^ k1 ^ 0x1BD11BDAu;
    uint32_t x0 = c0 + k0, x1 = c1 + k1;
#define TF_R(r) { x0 += x1; x1 = (x1 << (r)) | (x1 >> (32 - (r))); x1 ^= x0; }
    TF_R(13) TF_R(15) TF_R(26) TF_R(6)
    x0 += k1;  x1 += ks2 + 1u;
    TF_R(17) TF_R(29) TF_R(16) TF_R(24)
    x0 += ks2; x1 += k0 + 2u;
    TF_R(13) TF_R(15) TF_R(26) TF_R(6)
    x0 += k0;  x1 += k1 + 3u;
    TF_R(17) TF_R(29) TF_R(16) TF_R(24)
    x0 += k1;  x1 += ks2 + 4u;
    TF_R(13) TF_R(15) TF_R(26) TF_R(6)
    x0 += ks2; x1 += k0 + 5u;
#undef TF_R
    o0 = x0; o1 = x1;
}
__host__ __device__ __forceinline__ uint32_t tf_bits(uint32_t k0, uint32_t k1, uint32_t idx) {
    uint32_t o0, o1;
    threefry2x32(k0, k1, 0u, idx, o0, o1);
    return o0 ^ o1;
}

// ---------------------------------------------------------------------------
__global__ void normalize_kernel(const float* __restrict__ z1,
                                 const float* __restrict__ z2) {
    int gw = (blockIdx.x * blockDim.x + threadIdx.x) >> 5;
    int lane = threadIdx.x & 31;
    if (gw >= 2 * 4 * NT) return;
    const float* src;
    float* dst;
    if (gw < 4 * NT) { src = z1 + (size_t)gw * CD; dst = g_z1n + (size_t)gw * CD; }
    else { int r = gw - 4 * NT; src = z2 + (size_t)r * CD; dst = g_z2n + (size_t)r * CD; }
    float a[24];
    float s = 0.f;
#pragma unroll
    for (int u = 0; u < 24; u++) { float v = src[lane + u * 32]; a[u] = v; s += v * v; }
#pragma unroll
    for (int off = 16; off; off >>= 1) s += __shfl_xor_sync(0xffffffffu, s, off);
    float inv = rsqrtf(s + 1e-12f);
    if (lane == 0) { g_sq[gw] = s; g_inv[gw] = inv; }
#pragma unroll
    for (int u = 0; u < 24; u++) dst[lane + u * 32] = a[u] * inv;
}

// ---------------------------------------------------------------------------
// f32x2 GEMM body shared by both variants
// ---------------------------------------------------------------------------
#define GEMM_BODY(Ag, Bg)                                                        \
    unsigned long long acc2[8][4];                                               \
    _Pragma("unroll")                                                            \
    for (int i = 0; i < 8; i++)                                                  \
        _Pragma("unroll")                                                        \
        for (int j = 0; j < 4; j++) acc2[i][j] = 0ull;                           \
    for (int kk = 0; kk < CD; kk += 16) {                                        \
        float4 a0 = *(const float4*)(Ag + (size_t)lr * CD + kk + lc);            \
        float4 a1 = *(const float4*)(Ag + (size_t)(lr + 64) * CD + kk + lc);     \
        float4 b0 = *(const float4*)(Bg + (size_t)lr * CD + kk + lc);            \
        float4 b1 = *(const float4*)(Bg + (size_t)(lr + 64) * CD + kk + lc);     \
        __syncthreads();                                                         \
        As[lc + 0][lr] = a0.x; As[lc + 1][lr] = a0.y; As[lc + 2][lr] = a0.z; As[lc + 3][lr] = a0.w; \
        As[lc + 0][lr + 64] = a1.x; As[lc + 1][lr + 64] = a1.y; As[lc + 2][lr + 64] = a1.z; As[lc + 3][lr + 64] = a1.w; \
        Bs[lc + 0][lr] = b0.x; Bs[lc + 1][lr] = b0.y; Bs[lc + 2][lr] = b0.z; Bs[lc + 3][lr] = b0.w; \
        Bs[lc + 0][lr + 64] = b1.x; Bs[lc + 1][lr + 64] = b1.y; Bs[lc + 2][lr + 64] = b1.z; Bs[lc + 3][lr + 64] = b1.w; \
        __syncthreads();                                                         \
        _Pragma("unroll")                                                        \
        for (int k = 0; k < 16; k++) {                                           \
            float4 av0 = *(const float4*)(&As[k][ty * 8]);                       \
            float4 av1 = *(const float4*)(&As[k][ty * 8 + 4]);                   \
            float ar[8] = {av0.x, av0.y, av0.z, av0.w, av1.x, av1.y, av1.z, av1.w}; \
            const ulonglong2* bpq = (const ulonglong2*)(&Bs[k][tx * 8]);         \
            ulonglong2 bq0 = bpq[0], bq1 = bpq[1];                               \
            unsigned long long bp[4] = {bq0.x, bq0.y, bq1.x, bq1.y};             \
            _Pragma("unroll")                                                    \
            for (int i = 0; i < 8; i++) {                                        \
                unsigned long long ai;                                           \
                asm("mov.b64 %0, {%1, %1};" : "=l"(ai) : "f"(ar[i]));            \
                _Pragma("unroll")                                                \
                for (int j = 0; j < 4; j++)                                      \
                    asm("fma.rn.f32x2 %0, %1, %2, %0;" : "+l"(acc2[i][j]) : "l"(ai), "l"(bp[j])); \
            }                                                                    \
        }                                                                        \
    }

// Cross GEMM: full grid (16,16)
__global__ __launch_bounds__(256, 2) void gemm_kernel(
    const float* __restrict__ A, const float* __restrict__ B, float* __restrict__ S)
{
    __shared__ float As[16][128];
    __shared__ float Bs[16][128];
    int tid = threadIdx.x;
    int tx = tid & 15, ty = tid >> 4;
    int lr = tid >> 2, lc = (tid & 3) << 2;
    const float* Ag = A + (size_t)(blockIdx.y * 128) * CD;
    const float* Bg = B + (size_t)(blockIdx.x * 128) * CD;
    GEMM_BODY(Ag, Bg)
    int rb = blockIdx.y * 128 + ty * 8;
    int cb = blockIdx.x * 128 + tx * 8;
#pragma unroll
    for (int i = 0; i < 8; i++) {
        float o[8];
#pragma unroll
        for (int j = 0; j < 4; j++)
            asm("mov.b64 {%0, %1}, %2;" : "=f"(o[2 * j]), "=f"(o[2 * j + 1]) : "l"(acc2[i][j]));
        float4* dst = (float4*)(S + (size_t)(rb + i) * NT + cb);
        dst[0] = make_float4(o[0], o[1], o[2], o[3]);
        dst[1] = make_float4(o[4], o[5], o[6], o[7]);
    }
}

// Symmetric self GEMM: compute bx >= by only, mirror-store off-diagonal tiles.
__global__ __launch_bounds__(256, 2) void gemm_sym_kernel(
    const float* __restrict__ A, float* __restrict__ S)
{
    if (blockIdx.x < blockIdx.y) return;
    __shared__ float As[16][128];
    __shared__ float Bs[16][128];
    int tid = threadIdx.x;
    int tx = tid & 15, ty = tid >> 4;
    int lr = tid >> 2, lc = (tid & 3) << 2;
    const float* Ag = A + (size_t)(blockIdx.y * 128) * CD;
    const float* Bg = A + (size_t)(blockIdx.x * 128) * CD;
    GEMM_BODY(Ag, Bg)
    int rb = blockIdx.y * 128 + ty * 8;
    int cb = blockIdx.x * 128 + tx * 8;
#pragma unroll
    for (int i = 0; i < 8; i++) {
        float o[8];
#pragma unroll
        for (int j = 0; j < 4; j++)
            asm("mov.b64 {%0, %1}, %2;" : "=f"(o[2 * j]), "=f"(o[2 * j + 1]) : "l"(acc2[i][j]));
        float4* dst = (float4*)(S + (size_t)(rb + i) * NT + cb);
        dst[0] = make_float4(o[0], o[1], o[2], o[3]);
        dst[1] = make_float4(o[4], o[5], o[6], o[7]);
    }
    if (blockIdx.x != blockIdx.y) {
#pragma unroll
        for (int j = 0; j < 8; j++) {
            float ot[8];
#pragma unroll
            for (int i = 0; i < 8; i++) {
                float lo, hi;
                asm("mov.b64 {%0, %1}, %2;" : "=f"(lo), "=f"(hi) : "l"(acc2[i][j >> 1]));
                ot[i] = (j & 1) ? hi : lo;
            }
            float4* dst = (float4*)(S + (size_t)(cb + j) * NT + rb);
            dst[0] = make_float4(ot[0], ot[1], ot[2], ot[3]);
            dst[1] = make_float4(ot[4], ot[5], ot[6], ot[7]);
        }
    }
}

// ---------------------------------------------------------------------------
// Dual-mode self select: one block (4 warps) per row, reads S once, computes
// top-6 of sq-dist (CB) and top-6 of cos-dist (DA). Stable (value,index) ties.
// ---------------------------------------------------------------------------
__global__ void self_select_kernel(const float* __restrict__ S,
                                   int* __restrict__ neighCB, int* __restrict__ neighDA,
                                   const float* __restrict__ sqv,
                                   const float* __restrict__ invv, int wantDA) {
    __shared__ float svA[24], svB[24];
    __shared__ int   siA[24], siB[24];
    int row = blockIdx.x;
    int wid = threadIdx.x >> 5, lane = threadIdx.x & 31;
    float msq = sqv[row], minv = invv[row];

    float av[6]; int ai[6];
    float bv[6]; int bi[6];
#pragma unroll
    for (int u = 0; u < 6; u++) { av[u] = INFF; ai[u] = 0x7fffffff; bv[u] = INFF; bi[u] = 0x7fffffff; }

    const float* r = S + (size_t)row * NT;
    int jend = wid * 512 + 512;
    for (int j = wid * 512 + lane; j < jend; j += 32) {
        float dot = r[j];
        float v0 = fmaxf(msq + sqv[j] - 2.f * dot, 0.f);
        if (v0 < av[5] || (v0 == av[5] && j < ai[5])) {
            int pos = 5;
            while (pos > 0 && (v0 < av[pos - 1] || (v0 == av[pos - 1] && j < ai[pos - 1]))) {
                av[pos] = av[pos - 1]; ai[pos] = ai[pos - 1]; pos--;
            }
            av[pos] = v0; ai[pos] = j;
        }
        float v1 = 1.f - dot * minv * invv[j];
        if (v1 < bv[5] || (v1 == bv[5] && j < bi[5])) {
            int pos = 5;
            while (pos > 0 && (v1 < bv[pos - 1] || (v1 == bv[pos - 1] && j < bi[pos - 1]))) {
                bv[pos] = bv[pos - 1]; bi[pos] = bi[pos - 1]; pos--;
            }
            bv[pos] = v1; bi[pos] = j;
        }
    }
    // per-warp extract 6 best (asc) into smem
    for (int t = 0; t < 6; t++) {
        float v = av[0]; int id = ai[0];
#pragma unroll
        for (int off = 16; off; off >>= 1) {
            float ov = __shfl_down_sync(0xffffffffu, v, off);
            int oi = __shfl_down_sync(0xffffffffu, id, off);
            if (ov < v || (ov == v && oi < id)) { v = ov; id = oi; }
        }
        v = __shfl_sync(0xffffffffu, v, 0);
        id = __shfl_sync(0xffffffffu, id, 0);
        if (ai[0] == id) {
#pragma unroll
            for (int u = 0; u < 5; u++) { av[u] = av[u + 1]; ai[u] = ai[u + 1]; }
            av[5] = INFF; ai[5] = 0x7fffffff;
        }
        if (lane == 0) { svA[wid * 6 + t] = v; siA[wid * 6 + t] = id; }

        float w = bv[0]; int wd = bi[0];
#pragma unroll
        for (int off = 16; off; off >>= 1) {
            float ov = __shfl_down_sync(0xffffffffu, w, off);
            int oi = __shfl_down_sync(0xffffffffu, wd, off);
            if (ov < w || (ov == w && oi < wd)) { w = ov; wd = oi; }
        }
        w = __shfl_sync(0xffffffffu, w, 0);
        wd = __shfl_sync(0xffffffffu, wd, 0);
        if (bi[0] == wd) {
#pragma unroll
            for (int u = 0; u < 5; u++) { bv[u] = bv[u + 1]; bi[u] = bi[u + 1]; }
            bv[5] = INFF; bi[5] = 0x7fffffff;
        }
        if (lane == 0) { svB[wid * 6 + t] = w; siB[wid * 6 + t] = wd; }
    }
    __syncthreads();
    // warp0 merges mode A, warp1 merges mode B
    if (wid == 0) {
        float v = (lane < 24) ? svA[lane] : INFF;
        int id = (lane < 24) ? siA[lane] : 0x7fffffff;
        for (int t = 0; t < 6; t++) {
            float wv = v; int wi = id;
#pragma unroll
            for (int off = 16; off; off >>= 1) {
                float ov = __shfl_down_sync(0xffffffffu, wv, off);
                int oi = __shfl_down_sync(0xffffffffu, wi, off);
                if (ov < wv || (ov == wv && oi < wi)) { wv = ov; wi = oi; }
            }
            wi = __shfl_sync(0xffffffffu, wi, 0);
            if (id == wi) { v = INFF; id = 0x7fffffff; }
            if (t > 0 && lane == 0) neighCB[row * 5 + t - 1] = wi;
        }
    } else if (wid == 1 && wantDA) {
        float v = (lane < 24) ? svB[lane] : INFF;
        int id = (lane < 24) ? siB[lane] : 0x7fffffff;
        for (int t = 0; t < 6; t++) {
            float wv = v; int wi = id;
#pragma unroll
            for (int off = 16; off; off >>= 1) {
                float ov = __shfl_down_sync(0xffffffffu, wv, off);
                int oi = __shfl_down_sync(0xffffffffu, wi, off);
                if (ov < wv || (ov == wv && oi < wi)) { wv = ov; wi = oi; }
            }
            wi = __shfl_sync(0xffffffffu, wi, 0);
            if (id == wi) { v = INFF; id = 0x7fffffff; }
            if (t > 0 && lane == 0) neighDA[row * 5 + t - 1] = wi;
        }
    }
}

// ---------------------------------------------------------------------------
__global__ void cbneg_kernel(uint32_t k0, uint32_t k1,
                             const int* __restrict__ neigh, int* __restrict__ neg) {
    __shared__ float sv[20];
    __shared__ int   si[20];
    int row = blockIdx.x;
    int wid = threadIdx.x >> 5, lane = threadIdx.x & 31;
    int n0 = neigh[row * 5 + 0], n1 = neigh[row * 5 + 1], n2 = neigh[row * 5 + 2],
        n3 = neigh[row * 5 + 3], n4 = neigh[row * 5 + 4];
    float bv[5]; int bi[5];
#pragma unroll
    for (int u = 0; u < 5; u++) { bv[u] = NINFF; bi[u] = 0x7fffffff; }
    int jend = wid * 512 + 512;
    for (int j = wid * 512 + lane; j < jend; j += 32) {
        if (j == row || j == n0 || j == n1 || j == n2 || j == n3 || j == n4) continue;
        uint32_t bits = tf_bits(k0, k1, (uint32_t)(row * NT + j));
        float v = __uint_as_float((bits >> 9) | 0x3f800000u) - 1.0f;
        if (v > bv[4] || (v == bv[4] && j < bi[4])) {
            int pos = 4;
            while (pos > 0 && (v > bv[pos - 1] || (v == bv[pos - 1] && j < bi[pos - 1]))) {
                bv[pos] = bv[pos - 1]; bi[pos] = bi[pos - 1]; pos--;
            }
            bv[pos] = v; bi[pos] = j;
        }
    }
    for (int t = 0; t < 5; t++) {
        float v = bv[0]; int id = bi[0];
#pragma unroll
        for (int off = 16; off; off >>= 1) {
            float ov = __shfl_down_sync(0xffffffffu, v, off);
            int oi = __shfl_down_sync(0xffffffffu, id, off);
            if (ov > v || (ov == v && oi < id)) { v = ov; id = oi; }
        }
        v = __shfl_sync(0xffffffffu, v, 0);
        id = __shfl_sync(0xffffffffu, id, 0);
        if (bi[0] == id) {
#pragma unroll
            for (int u = 0; u < 4; u++) { bv[u] = bv[u + 1]; bi[u] = bi[u + 1]; }
            bv[4] = NINFF; bi[4] = 0x7fffffff;
        }
        if (lane == 0) { sv[wid * 5 + t] = v; si[wid * 5 + t] = id; }
    }
    __syncthreads();
    if (wid == 0) {
        float v = (lane < 20) ? sv[lane] : NINFF;
        int id = (lane < 20) ? si[lane] : 0x7fffffff;
        for (int t = 0; t < 5; t++) {
            float wv = v; int wi = id;
#pragma unroll
            for (int off = 16; off; off >>= 1) {
                float ov = __shfl_down_sync(0xffffffffu, wv, off);
                int oi = __shfl_down_sync(0xffffffffu, wi, off);
                if (ov > wv || (ov == wv && oi < wi)) { wv = ov; wi = oi; }
            }
            wi = __shfl_sync(0xffffffffu, wi, 0);
            if (id == wi) { v = NINFF; id = 0x7fffffff; }
            if (lane == 0) neg[row * 5 + t] = wi;
        }
    }
}

// ---------------------------------------------------------------------------
__global__ void cbloss_kernel(const float* __restrict__ An,
                              const int* __restrict__ neigh,
                              const int* __restrict__ neg,
                              float* __restrict__ rowbuf) {
    int row = (blockIdx.x * blockDim.x + threadIdx.x) >> 5;
    int lane = threadIdx.x & 31;
    if (row >= NT) return;
    float a[24];
    const float* ar = An + (size_t)row * CD;
#pragma unroll
    for (int u = 0; u < 24; u++) a[u] = ar[lane + u * 32];
    float s = 0.f;
    for (int k = 0; k < 5; k++) {
        const float* pr = An + (size_t)neigh[row * 5 + k] * CD;
        const float* nr = An + (size_t)neg[row * 5 + k] * CD;
        float dp = 0.f, dn = 0.f;
#pragma unroll
        for (int u = 0; u < 24; u++) {
            dp += a[u] * pr[lane + u * 32];
            dn += a[u] * nr[lane + u * 32];
        }
#pragma unroll
        for (int off = 16; off; off >>= 1) {
            dp += __shfl_xor_sync(0xffffffffu, dp, off);
            dn += __shfl_xor_sync(0xffffffffu, dn, off);
        }
        float sp = fminf(fmaxf(dp, -1.f), 1.f);
        float sn = fminf(fmaxf(dn, -1.f), 1.f);
        s += fmaxf(sn - sp + 0.05f, 0.f);
    }
    if (lane == 0) rowbuf[row] = s;
}

// ---------------------------------------------------------------------------
// argmin over a row of (1 - dot): one block (4 warps) per row.
// ---------------------------------------------------------------------------
__global__ void argmin_rows_kernel(const float* __restrict__ S, int* __restrict__ out) {
    __shared__ float sv[4];
    __shared__ int   si[4];
    int row = blockIdx.x;
    int wid = threadIdx.x >> 5, lane = threadIdx.x & 31;
    const float* r = S + (size_t)row * NT;
    float bv = INFF; int bi = 0x7fffffff;
    int jend = wid * 512 + 512;
    for (int j = wid * 512 + lane; j < jend; j += 32) {
        float v = 1.f - r[j];
        if (v < bv || (v == bv && j < bi)) { bv = v; bi = j; }
    }
#pragma unroll
    for (int off = 16; off; off >>= 1) {
        float ov = __shfl_down_sync(0xffffffffu, bv, off);
        int oi = __shfl_down_sync(0xffffffffu, bi, off);
        if (ov < bv || (ov == bv && oi < bi)) { bv = ov; bi = oi; }
    }
    if (lane == 0) { sv[wid] = bv; si[wid] = bi; }
    __syncthreads();
    if (threadIdx.x == 0) {
        float v = sv[0]; int id = si[0];
#pragma unroll
        for (int u = 1; u < 4; u++) {
            if (sv[u] < v || (sv[u] == v && si[u] < id)) { v = sv[u]; id = si[u]; }
        }
        out[row] = id;
    }
}

__global__ void argmin_cols_kernel(const float* __restrict__ S, int* __restrict__ out) {
    __shared__ float sv[32][33];
    __shared__ int   si[32][33];
    int tx = threadIdx.x, ty = threadIdx.y;
    int c = blockIdx.x * 32 + tx;
    float bv = INFF; int bi = 0x7fffffff;
    for (int r0 = 0; r0 < NT; r0 += 32) {
        int r = r0 + ty;
        float v = 1.f - S[(size_t)r * NT + c];
        if (v < bv || (v == bv && r < bi)) { bv = v; bi = r; }
    }
    sv[ty][tx] = bv; si[ty][tx] = bi;
    __syncthreads();
    if (ty == 0) {
        float v = sv[0][tx]; int id = si[0][tx];
#pragma unroll
        for (int u = 1; u < 32; u++) {
            float ov = sv[u][tx]; int oi = si[u][tx];
            if (ov < v || (ov == v && oi < id)) { v = ov; id = oi; }
        }
        out[c] = id;
    }
}

// ---------------------------------------------------------------------------
__global__ void mutual_order_kernel(const int* __restrict__ bofa,
                                    const int* __restrict__ aofb,
                                    int* __restrict__ idxB, int* __restrict__ order,
                                    int* __restrict__ negc) {
    __shared__ int matchs[NT];
    __shared__ int cnt[256];
    __shared__ int excl[257];
    int t = threadIdx.x;
    for (int i = t; i < NT; i += 256) matchs[i] = 0;
    __syncthreads();
    int base = t * 8;
#pragma unroll
    for (int u = 0; u < 8; u++) {
        int i = base + u;
        int b = bofa[i];
        int v = (aofb[b] == i) ? b : -1;
        idxB[i] = v;
        if (v >= 0) matchs[v] = 1;
    }
    __syncthreads();
    int m[8]; int c = 0;
#pragma unroll
    for (int u = 0; u < 8; u++) { m[u] = matchs[base + u]; c += (m[u] == 0); }
    cnt[t] = c;
    __syncthreads();
    if (t == 0) {
        int s = 0;
        for (int i = 0; i < 256; i++) { excl[i] = s; s += cnt[i]; }
        excl[256] = s;
    }
    __syncthreads();
    int Utot = excl[256];
    int u = excl[t];
    int mm = base - u;
#pragma unroll
    for (int x = 0; x < 8; x++) {
        if (m[x] == 0) order[u++] = base + x;
        else           order[Utot + mm++] = base + x;
    }
    if (t == 0) *negc = (Utot > 0) ? Utot : 1;
}

// ---------------------------------------------------------------------------
__global__ void nrcloss_kernel(const float* __restrict__ Bn,
                               const int* __restrict__ idxB,
                               const int* __restrict__ neighA,
                               const int* __restrict__ order,
                               const int* __restrict__ negcp,
                               uint32_t k0, uint32_t k1,
                               float* __restrict__ rowbuf, float* __restrict__ cntbuf) {
    int i = (blockIdx.x * blockDim.x + threadIdx.x) >> 5;
    int lane = threadIdx.x & 31;
    if (i >= NT) return;
    int ib = idxB[i];
    int uB = ib < 0 ? 0 : ib;
    int nc = *negcp;
    float a[24];
    const float* ar = Bn + (size_t)uB * CD;
#pragma unroll
    for (int u = 0; u < 24; u++) a[u] = ar[lane + u * 32];
    float hs = 0.f; int npos = 0;
    for (int k = 0; k < 5; k++) {
        int pb = idxB[neighA[i * 5 + k]];
        uint32_t bits = tf_bits(k0, k1, 10240u + (uint32_t)(i * 5 + k));
        int nb = order[(int)(bits & 2047u) % nc];
        const float* pr = Bn + (size_t)(pb < 0 ? 0 : pb) * CD;
        const float* nr = Bn + (size_t)nb * CD;
        float dp = 0.f, dn = 0.f;
#pragma unroll
        for (int u = 0; u < 24; u++) {
            dp += a[u] * pr[lane + u * 32];
            dn += a[u] * nr[lane + u * 32];
        }
#pragma unroll
        for (int off = 16; off; off >>= 1) {
            dp += __shfl_xor_sync(0xffffffffu, dp, off);
            dn += __shfl_xor_sync(0xffffffffu, dn, off);
        }
        if (pb >= 0) { hs += fmaxf(dn - dp + 0.4f, 0.f); npos++; }
    }
    if (lane == 0) {
        float per = hs / (float)(npos > 0 ? npos : 1);
        int valid = (ib >= 0) && (npos > 0);
        rowbuf[i] = valid ? per : 0.f;
        cntbuf[i] = valid ? 1.f : 0.f;
    }
}

// ---------------------------------------------------------------------------
__global__ void reduce_kernel(const float* __restrict__ buf, float* __restrict__ dst, float scale) {
    __shared__ float sh[1024];
    int t = threadIdx.x;
    sh[t] = buf[t] + buf[t + 1024];
    __syncthreads();
    for (int s = 512; s; s >>= 1) {
        if (t < s) sh[t] += sh[t + s];
        __syncthreads();
    }
    if (t == 0) *dst = sh[0] * scale;
}

// Fused dual reduce: block 0 sums rowbuf -> dstA, block 1 sums cntbuf -> dstB.
__global__ void reduce2_kernel(const float* __restrict__ bufA, const float* __restrict__ bufB,
                               float* __restrict__ dstA, float* __restrict__ dstB) {
    __shared__ float sh[1024];
    int t = threadIdx.x;
    const float* buf = blockIdx.x ? bufB : bufA;
    sh[t] = buf[t] + buf[t + 1024];
    __syncthreads();
    for (int s = 512; s; s >>= 1) {
        if (t < s) sh[t] += sh[t + s];
        __syncthreads();
    }
    if (t == 0) *(blockIdx.x ? dstB : dstA) = sh[0];
}

__global__ void final_kernel(float* __restrict__ out) {
    float l2 = 0.f;
    for (int i = 0; i < 8; i++) l2 += g_slots[i];
    l2 *= 0.25f;
    float l3 = 0.f;
    for (int s = 0; s < 2; s++) {
        float acc = 0.f;
        for (int j = 0; j < 6; j++) {
            int pi = s * 6 + j;
            float cn = g_slots[20 + pi];
            float sm = g_slots[8 + pi];
            acc += (cn > 0.f) ? sm / fmaxf(cn, 1.f) : 0.f;
        }
        l3 += acc / 6.f;
    }
    out[0] = 10.f * l2 + 10.f * l3;
}

// ---------------------------------------------------------------------------
namespace {
struct HostMT { uint32_t mt[624]; int pos; };
static void mt_seed(HostMT& s, uint32_t seed) {
    for (int p = 0; p < 624; p++) {
        s.mt[p] = seed;
        seed = 1812433253u * (seed ^ (seed >> 30)) + (uint32_t)p + 1u;
    }
    s.pos = 624;
}
static uint32_t mt_next(HostMT& s) {
    if (s.pos == 624) {
        for (int i = 0; i < 624; i++) {
            uint32_t y = (s.mt[i] & 0x80000000u) | (s.mt[(i + 1) % 624] & 0x7fffffffu);
            s.mt[i] = s.mt[(i + 397) % 624] ^ (y >> 1) ^ ((y & 1u) ? 0x9908b0dfu : 0u);
        }
        s.pos = 0;
    }
    uint32_t y = s.mt[s.pos++];
    y ^= y >> 11;
    y ^= (y << 7) & 0x9d2c5680u;
    y ^= (y << 15) & 0xefc60000u;
    y ^= y >> 18;
    return y;
}
static uint32_t mt_interval(HostMT& s, uint32_t mx) {
    if (mx == 0) return 0;
    uint32_t mask = mx;
    mask |= mask >> 1; mask |= mask >> 2; mask |= mask >> 4;
    mask |= mask >> 8; mask |= mask >> 16;
    uint32_t v;
    while ((v = (mt_next(s) & mask)) > mx) {}
    return v;
}
static void perm12(uint32_t seed, int* out) {
    HostMT s; mt_seed(s, seed);
    for (int i = 0; i < 12; i++) out[i] = i;
    for (int i = 11; i > 0; i--) {
        int j = (int)mt_interval(s, (uint32_t)i);
        int t = out[i]; out[i] = out[j]; out[j] = t;
    }
}
}  // namespace

// ---------------------------------------------------------------------------
extern "C" void kernel_launch(void* const* d_in, const int* in_sizes, int n_in,
                              void* d_out, int out_size) {
    const float* z1 = (const float*)d_in[0];
    const float* z2 = (const float*)d_in[1];
    float* out = (float*)d_out;

    float *z1n, *z2n, *sq, *invv, *S, *rowbuf, *cntbuf, *slots;
    int *neighCB, *negCB, *neighA, *bofa, *aofb, *idxB, *order, *negc;
    cudaGetSymbolAddress((void**)&z1n, g_z1n);
    cudaGetSymbolAddress((void**)&z2n, g_z2n);
    cudaGetSymbolAddress((void**)&sq, g_sq);
    cudaGetSymbolAddress((void**)&invv, g_inv);
    cudaGetSymbolAddress((void**)&S, g_S);
    cudaGetSymbolAddress((void**)&rowbuf, g_rowbuf);
    cudaGetSymbolAddress((void**)&cntbuf, g_cntbuf);
    cudaGetSymbolAddress((void**)&slots, g_slots);
    cudaGetSymbolAddress((void**)&neighCB, g_neighCB);
    cudaGetSymbolAddress((void**)&negCB, g_negCB);
    cudaGetSymbolAddress((void**)&neighA, g_neighA);
    cudaGetSymbolAddress((void**)&bofa, g_bofa);
    cudaGetSymbolAddress((void**)&aofb, g_aofb);
    cudaGetSymbolAddress((void**)&idxB, g_idxB);
    cudaGetSymbolAddress((void**)&order, g_order);
    cudaGetSymbolAddress((void**)&negc, g_negc);

    uint32_t ck[4][2];
    for (int i = 0; i < 4; i++)
        threefry2x32(0u, 42u, 0u, (uint32_t)i, ck[i][0], ck[i][1]);
    uint32_t cbk[2][4][2];
    for (int b = 0; b < 4; b++) {
        threefry2x32(ck[0][0], ck[0][1], 0u, (uint32_t)b, cbk[0][b][0], cbk[0][b][1]);
        threefry2x32(ck[1][0], ck[1][1], 0u, (uint32_t)b, cbk[1][b][0], cbk[1][b][1]);
    }
    uint32_t kp[12][2];
    for (int j = 0; j < 6; j++) {
        threefry2x32(ck[2][0], ck[2][1], 0u, (uint32_t)j, kp[j][0], kp[j][1]);
        threefry2x32(ck[3][0], ck[3][1], 0u, (uint32_t)j, kp[6 + j][0], kp[6 + j][1]);
    }

    int allp[12][2];
    { int t = 0;
      for (int p = 0; p < 4; p++)
          for (int q = 0; q < 4; q++)
              if (p != q) { allp[t][0] = p; allp[t][1] = q; t++; } }
    int pairs[12][2];
    int perm[12];
    perm12(0u, perm);
    for (int j = 0; j < 6; j++) { pairs[j][0] = allp[perm[j]][0]; pairs[j][1] = allp[perm[j]][1]; }
    perm12(1u, perm);
    for (int j = 0; j < 6; j++) { pairs[6 + j][0] = allp[perm[j]][0]; pairs[6 + j][1] = allp[perm[j]][1]; }

    const size_t MAT = (size_t)NT * CD;

    normalize_kernel<<<2048, 256>>>(z1, z2);

    bool needA[8];
    for (int s = 0; s < 8; s++) needA[s] = false;
    for (int pi = 0; pi < 12; pi++) needA[(pi / 6) * 4 + pairs[pi][0]] = true;

    // --- self GEMMs (symmetric) + fused dual select + crossbrain loss
    for (int s = 0; s < 8; s++) {
        int d = s >> 2, b = s & 3;
        const float* Araw = (d == 0 ? z1 : z2) + (size_t)b * MAT;
        const float* anch = (d == 0 ? z2n : z1n) + (size_t)b * MAT;
        const float* sqp = sq + (size_t)s * NT;
        const float* invp = invv + (size_t)s * NT;
        gemm_sym_kernel<<<dim3(16, 16), 256>>>(Araw, S);
        self_select_kernel<<<NT, 128>>>(S, neighCB, neighA + (size_t)s * NT * 5,
                                        sqp, invp, needA[s] ? 1 : 0);
        cbneg_kernel<<<NT, 128>>>(cbk[d][b][0], cbk[d][b][1], neighCB, negCB);
        cbloss_kernel<<<256, 256>>>(anch, neighCB, negCB, rowbuf);
        reduce_kernel<<<1, 1024>>>(rowbuf, slots + s, 1.0f / 10240.0f);
    }

    // --- NRC: build processing order with transpose dedup (host, deterministic)
    int procPi[12], procTrans[12], procGemm[12];
    bool used1[12] = {false};
    int np = 0;
    for (int j0 = 0; j0 < 6; j0++) {
        procPi[np] = j0; procTrans[np] = 0; procGemm[np] = 1; np++;
        for (int j1 = 6; j1 < 12; j1++) {
            if (!used1[j1] && pairs[j1][0] == pairs[j0][1] && pairs[j1][1] == pairs[j0][0]) {
                procPi[np] = j1; procTrans[np] = 1; procGemm[np] = 0; np++;
                used1[j1] = true;
                break;
            }
        }
    }
    for (int j1 = 6; j1 < 12; j1++)
        if (!used1[j1]) { procPi[np] = j1; procTrans[np] = 0; procGemm[np] = 1; np++; }

    for (int e = 0; e < np; e++) {
        int pi = procPi[e];
        int side = pi / 6, p = pairs[pi][0], q = pairs[pi][1];
        const float* An = (side == 0 ? z1n : z2n) + (size_t)p * MAT;
        const float* Bn = (side == 0 ? z2n : z1n) + (size_t)q * MAT;
        if (procGemm[e])
            gemm_kernel<<<dim3(16, 16), 256>>>(An, Bn, S);
        if (procTrans[e]) {
            argmin_cols_kernel<<<64, dim3(32, 32)>>>(S, bofa);
            argmin_rows_kernel<<<NT, 128>>>(S, aofb);
        } else {
            argmin_rows_kernel<<<NT, 128>>>(S, bofa);
            argmin_cols_kernel<<<64, dim3(32, 32)>>>(S, aofb);
        }
        mutual_order_kernel<<<1, 256>>>(bofa, aofb, idxB, order, negc);
        nrcloss_kernel<<<256, 256>>>(Bn, idxB, neighA + (size_t)(side * 4 + p) * NT * 5,
                                     order, negc, kp[pi][0], kp[pi][1], rowbuf, cntbuf);
        reduce2_kernel<<<2, 1024>>>(rowbuf, cntbuf, slots + 8 + pi, slots + 20 + pi);
    }

    final_kernel<<<1, 1>>>(out);
}

// round 10
// speedup vs baseline: 1.5843x; 1.5843x over previous
#include <cuda_runtime.h>
#include <cstdint>

#define NT 2048
#define CD 768
#define INFF  __int_as_float(0x7f800000)
#define NINFF __int_as_float(0xff800000)
typedef unsigned long long ull;

// ---------------------------------------------------------------------------
__device__ float g_z1n[4 * NT * CD];
__device__ float g_z2n[4 * NT * CD];
__device__ float g_sq[8 * NT];
__device__ float g_inv[8 * NT];
__device__ float g_Sself[8ULL * NT * NT];          // 128 MB
__device__ ull   g_rowmin[12 * NT];
__device__ ull   g_colmin[12 * NT];
__device__ int   g_neighCB[8 * NT * 5];
__device__ int   g_negCB[8 * NT * 5];
__device__ int   g_neighA[8 * NT * 5];
__device__ int   g_idxB[12 * NT];
__device__ int   g_order[12 * NT];
__device__ int   g_negc[12];
__device__ float g_rowCB[8 * NT];
__device__ float g_rowNRC[12 * NT];
__device__ float g_cntNRC[12 * NT];
__device__ float g_slots[32];

struct Cfg {
    int nU;
    int u_side[12], u_p[12], u_q[12];
    int pi_uslot[12], pi_swap[12];
    int pi_side[12], pi_p[12], pi_q[12];
    unsigned kp[12][2];
    unsigned cbk[8][2];
};

// ---------------------------------------------------------------------------
__host__ __device__ __forceinline__ void threefry2x32(
    uint32_t k0, uint32_t k1, uint32_t c0, uint32_t c1, uint32_t& o0, uint32_t& o1)
{
    uint32_t ks2 = k0 ^ k1 ^ 0x1BD11BDAu;
    uint32_t x0 = c0 + k0, x1 = c1 + k1;
#define TF_R(r) { x0 += x1; x1 = (x1 << (r)) | (x1 >> (32 - (r))); x1 ^= x0; }
    TF_R(13) TF_R(15) TF_R(26) TF_R(6)
    x0 += k1;  x1 += ks2 + 1u;
    TF_R(17) TF_R(29) TF_R(16) TF_R(24)
    x0 += ks2; x1 += k0 + 2u;
    TF_R(13) TF_R(15) TF_R(26) TF_R(6)
    x0 += k0;  x1 += k1 + 3u;
    TF_R(17) TF_R(29) TF_R(16) TF_R(24)
    x0 += k1;  x1 += ks2 + 4u;
    TF_R(13) TF_R(15) TF_R(26) TF_R(6)
    x0 += ks2; x1 += k0 + 5u;
#undef TF_R
    o0 = x0; o1 = x1;
}
__host__ __device__ __forceinline__ uint32_t tf_bits(uint32_t k0, uint32_t k1, uint32_t idx) {
    uint32_t o0, o1;
    threefry2x32(k0, k1, 0u, idx, o0, o1);
    return o0 ^ o1;
}
__device__ __forceinline__ ull packmin(float v, int idx) {
    unsigned u = __float_as_uint(v);
    u = (u & 0x80000000u) ? ~u : (u | 0x80000000u);
    return ((ull)u << 32) | (unsigned)idx;
}

// ---------------------------------------------------------------------------
__global__ void normalize_kernel(const float* __restrict__ z1,
                                 const float* __restrict__ z2) {
    int gw = (blockIdx.x * blockDim.x + threadIdx.x) >> 5;
    int lane = threadIdx.x & 31;
    if (gw >= 8 * NT) return;
    const float* src;
    float* dst;
    if (gw < 4 * NT) { src = z1 + (size_t)gw * CD; dst = g_z1n + (size_t)gw * CD; }
    else { int r = gw - 4 * NT; src = z2 + (size_t)r * CD; dst = g_z2n + (size_t)r * CD; }
    float a[24];
    float s = 0.f;
#pragma unroll
    for (int u = 0; u < 24; u++) { float v = src[lane + u * 32]; a[u] = v; s += v * v; }
#pragma unroll
    for (int off = 16; off; off >>= 1) s += __shfl_xor_sync(0xffffffffu, s, off);
    float inv = rsqrtf(s + 1e-12f);
    if (lane == 0) { g_sq[gw] = s; g_inv[gw] = inv; }
#pragma unroll
    for (int u = 0; u < 24; u++) dst[lane + u * 32] = a[u] * inv;
}

__global__ void init_kernel() {
    int i = blockIdx.x * blockDim.x + threadIdx.x;
    if (i < 12 * NT) { g_rowmin[i] = ~0ull; g_colmin[i] = ~0ull; }
}

// ---------------------------------------------------------------------------
#define GEMM_BODY(Ag, Bg)                                                        \
    unsigned long long acc2[8][4];                                               \
    _Pragma("unroll")                                                            \
    for (int i = 0; i < 8; i++)                                                  \
        _Pragma("unroll")                                                        \
        for (int j = 0; j < 4; j++) acc2[i][j] = 0ull;                           \
    for (int kk = 0; kk < CD; kk += 16) {                                        \
        float4 a0 = *(const float4*)(Ag + (size_t)lr * CD + kk + lc);            \
        float4 a1 = *(const float4*)(Ag + (size_t)(lr + 64) * CD + kk + lc);     \
        float4 b0 = *(const float4*)(Bg + (size_t)lr * CD + kk + lc);            \
        float4 b1 = *(const float4*)(Bg + (size_t)(lr + 64) * CD + kk + lc);     \
        __syncthreads();                                                         \
        As[lc + 0][lr] = a0.x; As[lc + 1][lr] = a0.y; As[lc + 2][lr] = a0.z; As[lc + 3][lr] = a0.w; \
        As[lc + 0][lr + 64] = a1.x; As[lc + 1][lr + 64] = a1.y; As[lc + 2][lr + 64] = a1.z; As[lc + 3][lr + 64] = a1.w; \
        Bs[lc + 0][lr] = b0.x; Bs[lc + 1][lr] = b0.y; Bs[lc + 2][lr] = b0.z; Bs[lc + 3][lr] = b0.w; \
        Bs[lc + 0][lr + 64] = b1.x; Bs[lc + 1][lr + 64] = b1.y; Bs[lc + 2][lr + 64] = b1.z; Bs[lc + 3][lr + 64] = b1.w; \
        __syncthreads();                                                         \
        _Pragma("unroll")                                                        \
        for (int k = 0; k < 16; k++) {                                           \
            float4 av0 = *(const float4*)(&As[k][ty * 8]);                       \
            float4 av1 = *(const float4*)(&As[k][ty * 8 + 4]);                   \
            float ar[8] = {av0.x, av0.y, av0.z, av0.w, av1.x, av1.y, av1.z, av1.w}; \
            const ulonglong2* bpq = (const ulonglong2*)(&Bs[k][tx * 8]);         \
            ulonglong2 bq0 = bpq[0], bq1 = bpq[1];                               \
            unsigned long long bp[4] = {bq0.x, bq0.y, bq1.x, bq1.y};             \
            _Pragma("unroll")                                                    \
            for (int i = 0; i < 8; i++) {                                        \
                unsigned long long ai;                                           \
                asm("mov.b64 %0, {%1, %1};" : "=l"(ai) : "f"(ar[i]));            \
                _Pragma("unroll")                                                \
                for (int j = 0; j < 4; j++)                                      \
                    asm("fma.rn.f32x2 %0, %1, %2, %0;" : "+l"(acc2[i][j]) : "l"(ai), "l"(bp[j])); \
            }                                                                    \
        }                                                                        \
    }

// Batched symmetric self GEMM: grid (16,16,8), skip bx<by, mirror via smem.
__global__ __launch_bounds__(256, 2) void gemm_self_kernel(
    const float* __restrict__ z1, const float* __restrict__ z2)
{
    if (blockIdx.x < blockIdx.y) return;
    __shared__ float sm[2][16][128];
    float (*As)[128] = sm[0];
    float (*Bs)[128] = sm[1];
    int z = blockIdx.z;
    const float* A = ((z >> 2) == 0 ? z1 : z2) + (size_t)(z & 3) * NT * CD;
    float* S = g_Sself + (size_t)z * NT * NT;
    int tid = threadIdx.x;
    int tx = tid & 15, ty = tid >> 4;
    int lr = tid >> 2, lc = (tid & 3) << 2;
    const float* Ag = A + (size_t)(blockIdx.y * 128) * CD;
    const float* Bg = A + (size_t)(blockIdx.x * 128) * CD;
    GEMM_BODY(Ag, Bg)
    int rb = blockIdx.y * 128 + ty * 8;
    int cb = blockIdx.x * 128 + tx * 8;
#pragma unroll
    for (int i = 0; i < 8; i++) {
        float o[8];
#pragma unroll
        for (int j = 0; j < 4; j++)
            asm("mov.b64 {%0, %1}, %2;" : "=f"(o[2 * j]), "=f"(o[2 * j + 1]) : "l"(acc2[i][j]));
        float4* dst = (float4*)(S + (size_t)(rb + i) * NT + cb);
        dst[0] = make_float4(o[0], o[1], o[2], o[3]);
        dst[1] = make_float4(o[4], o[5], o[6], o[7]);
    }
    if (blockIdx.x != blockIdx.y) {
        float* stage = &sm[0][0][0];   // 4096 floats = one 32x128 chunk
        int rb0 = blockIdx.y * 128, cb0 = blockIdx.x * 128;
        for (int c = 0; c < 4; c++) {
            __syncthreads();
            if ((tx >> 2) == c) {
#pragma unroll
                for (int j = 0; j < 8; j++) {
                    int jl = (tx & 3) * 8 + j;   // 0..31 within chunk
#pragma unroll
                    for (int i = 0; i < 8; i++) {
                        float lo, hi;
                        asm("mov.b64 {%0, %1}, %2;" : "=f"(lo), "=f"(hi) : "l"(acc2[i][j >> 1]));
                        stage[jl * 128 + ty * 8 + i] = (j & 1) ? hi : lo;
                    }
                }
            }
            __syncthreads();
            int row = tid >> 3, col = (tid & 7) * 16;
            float4* src4 = (float4*)(stage + row * 128 + col);
            float4* dst4 = (float4*)(S + (size_t)(cb0 + c * 32 + row) * NT + rb0 + col);
            dst4[0] = src4[0]; dst4[1] = src4[1]; dst4[2] = src4[2]; dst4[3] = src4[3];
        }
    }
}

// Batched fused cross GEMM + row/col argmin (no S materialization).
__global__ __launch_bounds__(256, 2) void gemm_cross_kernel(
    const float* __restrict__ z1n_, const float* __restrict__ z2n_, Cfg cfg)
{
    __shared__ float As[16][128];
    __shared__ float Bs[16][128];
    __shared__ ull smc[16][17];
    int u = blockIdx.z;
    int side = cfg.u_side[u];
    const float* A = (side == 0 ? z1n_ : z2n_) + (size_t)cfg.u_p[u] * NT * CD;
    const float* B = (side == 0 ? z2n_ : z1n_) + (size_t)cfg.u_q[u] * NT * CD;
    int tid = threadIdx.x;
    int tx = tid & 15, ty = tid >> 4;
    int lr = tid >> 2, lc = (tid & 3) << 2;
    const float* Ag = A + (size_t)(blockIdx.y * 128) * CD;
    const float* Bg = B + (size_t)(blockIdx.x * 128) * CD;
    GEMM_BODY(Ag, Bg)
    int rb = blockIdx.y * 128 + ty * 8;
    int cb = blockIdx.x * 128 + tx * 8;
    float v[8][8];
#pragma unroll
    for (int i = 0; i < 8; i++) {
#pragma unroll
        for (int j = 0; j < 4; j++) {
            float lo, hi;
            asm("mov.b64 {%0, %1}, %2;" : "=f"(lo), "=f"(hi) : "l"(acc2[i][j]));
            v[i][2 * j] = 1.f - lo; v[i][2 * j + 1] = 1.f - hi;
        }
    }
    // row argmins: reduce over 16 tx lanes (same ty, contiguous 16-lane group)
#pragma unroll
    for (int i = 0; i < 8; i++) {
        ull best = ~0ull;
#pragma unroll
        for (int j = 0; j < 8; j++) {
            ull pk = packmin(v[i][j], cb + j);
            if (pk < best) best = pk;
        }
#pragma unroll
        for (int m = 1; m < 16; m <<= 1) {
            ull o = __shfl_xor_sync(0xffffffffu, best, m);
            if (o < best) best = o;
        }
        if (tx == 0) atomicMin(&g_rowmin[u * NT + rb + i], best);
    }
    // col argmins: reduce over ty via smem
#pragma unroll
    for (int jj = 0; jj < 8; jj++) {
        ull best = ~0ull;
#pragma unroll
        for (int i = 0; i < 8; i++) {
            ull pk = packmin(v[i][jj], rb + i);
            if (pk < best) best = pk;
        }
        smc[ty][tx] = best;
        __syncthreads();
        if (tid < 16) {
            ull b = smc[0][tid];
#pragma unroll
            for (int r = 1; r < 16; r++) if (smc[r][tid] < b) b = smc[r][tid];
            atomicMin(&g_colmin[u * NT + blockIdx.x * 128 + tid * 8 + jj], b);
        }
        __syncthreads();
    }
}

// ---------------------------------------------------------------------------
// Batched dual-mode self select: grid (NT, 8), 4 warps, float4 loads.
// ---------------------------------------------------------------------------
__global__ void self_select_kernel() {
    __shared__ float svA[24], svB[24];
    __shared__ int   siA[24], siB[24];
    int row = blockIdx.x, s = blockIdx.y;
    int wid = threadIdx.x >> 5, lane = threadIdx.x & 31;
    const float* sqv = g_sq + (size_t)s * NT;
    const float* invv = g_inv + (size_t)s * NT;
    const float* r = g_Sself + (size_t)s * NT * NT + (size_t)row * NT;
    float msq = sqv[row], minv = invv[row];

    float av[6]; int ai[6];
    float bv[6]; int bi[6];
#pragma unroll
    for (int u = 0; u < 6; u++) { av[u] = INFF; ai[u] = 0x7fffffff; bv[u] = INFF; bi[u] = 0x7fffffff; }

    for (int it = 0; it < 4; it++) {
        int j0 = wid * 512 + it * 128 + lane * 4;
        float4 d4 = *(const float4*)(r + j0);
        float4 q4 = *(const float4*)(sqv + j0);
        float4 i4 = *(const float4*)(invv + j0);
        float dd[4] = {d4.x, d4.y, d4.z, d4.w};
        float qq[4] = {q4.x, q4.y, q4.z, q4.w};
        float ii[4] = {i4.x, i4.y, i4.z, i4.w};
#pragma unroll
        for (int c = 0; c < 4; c++) {
            int j = j0 + c;
            float v0 = fmaxf(msq + qq[c] - 2.f * dd[c], 0.f);
            if (v0 < av[5] || (v0 == av[5] && j < ai[5])) {
                int pos = 5;
                while (pos > 0 && (v0 < av[pos - 1] || (v0 == av[pos - 1] && j < ai[pos - 1]))) {
                    av[pos] = av[pos - 1]; ai[pos] = ai[pos - 1]; pos--;
                }
                av[pos] = v0; ai[pos] = j;
            }
            float v1 = 1.f - dd[c] * minv * ii[c];
            if (v1 < bv[5] || (v1 == bv[5] && j < bi[5])) {
                int pos = 5;
                while (pos > 0 && (v1 < bv[pos - 1] || (v1 == bv[pos - 1] && j < bi[pos - 1]))) {
                    bv[pos] = bv[pos - 1]; bi[pos] = bi[pos - 1]; pos--;
                }
                bv[pos] = v1; bi[pos] = j;
            }
        }
    }
    for (int t = 0; t < 6; t++) {
        float v = av[0]; int id = ai[0];
#pragma unroll
        for (int off = 16; off; off >>= 1) {
            float ov = __shfl_down_sync(0xffffffffu, v, off);
            int oi = __shfl_down_sync(0xffffffffu, id, off);
            if (ov < v || (ov == v && oi < id)) { v = ov; id = oi; }
        }
        v = __shfl_sync(0xffffffffu, v, 0);
        id = __shfl_sync(0xffffffffu, id, 0);
        if (ai[0] == id) {
#pragma unroll
            for (int u = 0; u < 5; u++) { av[u] = av[u + 1]; ai[u] = ai[u + 1]; }
            av[5] = INFF; ai[5] = 0x7fffffff;
        }
        if (lane == 0) { svA[wid * 6 + t] = v; siA[wid * 6 + t] = id; }
        float w = bv[0]; int wd = bi[0];
#pragma unroll
        for (int off = 16; off; off >>= 1) {
            float ov = __shfl_down_sync(0xffffffffu, w, off);
            int oi = __shfl_down_sync(0xffffffffu, wd, off);
            if (ov < w || (ov == w && oi < wd)) { w = ov; wd = oi; }
        }
        w = __shfl_sync(0xffffffffu, w, 0);
        wd = __shfl_sync(0xffffffffu, wd, 0);
        if (bi[0] == wd) {
#pragma unroll
            for (int u = 0; u < 5; u++) { bv[u] = bv[u + 1]; bi[u] = bi[u + 1]; }
            bv[5] = INFF; bi[5] = 0x7fffffff;
        }
        if (lane == 0) { svB[wid * 6 + t] = w; siB[wid * 6 + t] = wd; }
    }
    __syncthreads();
    if (wid < 2) {
        float* sv = wid ? svB : svA;
        int* si = wid ? siB : siA;
        int* outp = (wid ? g_neighA : g_neighCB) + (size_t)s * NT * 5 + row * 5;
        float v = (lane < 24) ? sv[lane] : INFF;
        int id = (lane < 24) ? si[lane] : 0x7fffffff;
        for (int t = 0; t < 6; t++) {
            float wv = v; int wi = id;
#pragma unroll
            for (int off = 16; off; off >>= 1) {
                float ov = __shfl_down_sync(0xffffffffu, wv, off);
                int oi = __shfl_down_sync(0xffffffffu, wi, off);
                if (ov < wv || (ov == wv && oi < wi)) { wv = ov; wi = oi; }
            }
            wi = __shfl_sync(0xffffffffu, wi, 0);
            if (id == wi) { v = INFF; id = 0x7fffffff; }
            if (t > 0 && lane == 0) outp[t - 1] = wi;
        }
    }
}

// ---------------------------------------------------------------------------
__global__ void cbneg_kernel(Cfg cfg) {
    __shared__ float sv[20];
    __shared__ int   si[20];
    int row = blockIdx.x, s = blockIdx.y;
    uint32_t k0 = cfg.cbk[s][0], k1 = cfg.cbk[s][1];
    const int* neigh = g_neighCB + (size_t)s * NT * 5;
    int* neg = g_negCB + (size_t)s * NT * 5;
    int wid = threadIdx.x >> 5, lane = threadIdx.x & 31;
    int n0 = neigh[row * 5 + 0], n1 = neigh[row * 5 + 1], n2 = neigh[row * 5 + 2],
        n3 = neigh[row * 5 + 3], n4 = neigh[row * 5 + 4];
    float bv[5]; int bi[5];
#pragma unroll
    for (int u = 0; u < 5; u++) { bv[u] = NINFF; bi[u] = 0x7fffffff; }
    int jend = wid * 512 + 512;
    for (int j = wid * 512 + lane; j < jend; j += 32) {
        if (j == row || j == n0 || j == n1 || j == n2 || j == n3 || j == n4) continue;
        uint32_t bits = tf_bits(k0, k1, (uint32_t)(row * NT + j));
        float v = __uint_as_float((bits >> 9) | 0x3f800000u) - 1.0f;
        if (v > bv[4] || (v == bv[4] && j < bi[4])) {
            int pos = 4;
            while (pos > 0 && (v > bv[pos - 1] || (v == bv[pos - 1] && j < bi[pos - 1]))) {
                bv[pos] = bv[pos - 1]; bi[pos] = bi[pos - 1]; pos--;
            }
            bv[pos] = v; bi[pos] = j;
        }
    }
    for (int t = 0; t < 5; t++) {
        float v = bv[0]; int id = bi[0];
#pragma unroll
        for (int off = 16; off; off >>= 1) {
            float ov = __shfl_down_sync(0xffffffffu, v, off);
            int oi = __shfl_down_sync(0xffffffffu, id, off);
            if (ov > v || (ov == v && oi < id)) { v = ov; id = oi; }
        }
        v = __shfl_sync(0xffffffffu, v, 0);
        id = __shfl_sync(0xffffffffu, id, 0);
        if (bi[0] == id) {
#pragma unroll
            for (int u = 0; u < 4; u++) { bv[u] = bv[u + 1]; bi[u] = bi[u + 1]; }
            bv[4] = NINFF; bi[4] = 0x7fffffff;
        }
        if (lane == 0) { sv[wid * 5 + t] = v; si[wid * 5 + t] = id; }
    }
    __syncthreads();
    if (wid == 0) {
        float v = (lane < 20) ? sv[lane] : NINFF;
        int id = (lane < 20) ? si[lane] : 0x7fffffff;
        for (int t = 0; t < 5; t++) {
            float wv = v; int wi = id;
#pragma unroll
            for (int off = 16; off; off >>= 1) {
                float ov = __shfl_down_sync(0xffffffffu, wv, off);
                int oi = __shfl_down_sync(0xffffffffu, wi, off);
                if (ov > wv || (ov == wv && oi < wi)) { wv = ov; wi = oi; }
            }
            wi = __shfl_sync(0xffffffffu, wi, 0);
            if (id == wi) { v = NINFF; id = 0x7fffffff; }
            if (lane == 0) neg[row * 5 + t] = wi;
        }
    }
}

// ---------------------------------------------------------------------------
__global__ void cbloss_kernel(const float* __restrict__ z1n_,
                              const float* __restrict__ z2n_) {
    int s = blockIdx.y;
    int row = (blockIdx.x * blockDim.x + threadIdx.x) >> 5;
    int lane = threadIdx.x & 31;
    if (row >= NT) return;
    const float* An = (s < 4 ? z2n_ : z1n_) + (size_t)(s & 3) * NT * CD;
    const int* neigh = g_neighCB + (size_t)s * NT * 5;
    const int* neg = g_negCB + (size_t)s * NT * 5;
    float a[24];
    const float* ar = An + (size_t)row * CD;
#pragma unroll
    for (int u = 0; u < 24; u++) a[u] = ar[lane + u * 32];
    float sacc = 0.f;
    for (int k = 0; k < 5; k++) {
        const float* pr = An + (size_t)neigh[row * 5 + k] * CD;
        const float* nr = An + (size_t)neg[row * 5 + k] * CD;
        float dp = 0.f, dn = 0.f;
#pragma unroll
        for (int u = 0; u < 24; u++) {
            dp += a[u] * pr[lane + u * 32];
            dn += a[u] * nr[lane + u * 32];
        }
#pragma unroll
        for (int off = 16; off; off >>= 1) {
            dp += __shfl_xor_sync(0xffffffffu, dp, off);
            dn += __shfl_xor_sync(0xffffffffu, dn, off);
        }
        float sp = fminf(fmaxf(dp, -1.f), 1.f);
        float sn = fminf(fmaxf(dn, -1.f), 1.f);
        sacc += fmaxf(sn - sp + 0.05f, 0.f);
    }
    if (lane == 0) g_rowCB[s * NT + row] = sacc;
}

// ---------------------------------------------------------------------------
__global__ void mutual_order_kernel(Cfg cfg) {
    __shared__ int matchs[NT];
    __shared__ int cnt[256];
    __shared__ int excl[257];
    int pi = blockIdx.x;
    int u = cfg.pi_uslot[pi], sw = cfg.pi_swap[pi];
    const ull* rm = (sw ? g_colmin : g_rowmin) + (size_t)u * NT;  // bofa
    const ull* cm = (sw ? g_rowmin : g_colmin) + (size_t)u * NT;  // aofb
    int* idxB = g_idxB + (size_t)pi * NT;
    int* order = g_order + (size_t)pi * NT;
    int t = threadIdx.x;
    for (int i = t; i < NT; i += 256) matchs[i] = 0;
    __syncthreads();
    int base = t * 8;
#pragma unroll
    for (int uu = 0; uu < 8; uu++) {
        int i = base + uu;
        int b = (int)(rm[i] & 0xffffffffu);
        int v = ((int)(cm[b] & 0xffffffffu) == i) ? b : -1;
        idxB[i] = v;
        if (v >= 0) matchs[v] = 1;
    }
    __syncthreads();
    int m[8]; int c = 0;
#pragma unroll
    for (int uu = 0; uu < 8; uu++) { m[uu] = matchs[base + uu]; c += (m[uu] == 0); }
    cnt[t] = c;
    __syncthreads();
    if (t == 0) {
        int s = 0;
        for (int i = 0; i < 256; i++) { excl[i] = s; s += cnt[i]; }
        excl[256] = s;
    }
    __syncthreads();
    int Utot = excl[256];
    int uo = excl[t];
    int mm = base - uo;
#pragma unroll
    for (int x = 0; x < 8; x++) {
        if (m[x] == 0) order[uo++] = base + x;
        else           order[Utot + mm++] = base + x;
    }
    if (t == 0) g_negc[pi] = (Utot > 0) ? Utot : 1;
}

// ---------------------------------------------------------------------------
__global__ void nrcloss_kernel(const float* __restrict__ z1n_,
                               const float* __restrict__ z2n_, Cfg cfg) {
    int pi = blockIdx.y;
    int i = (blockIdx.x * blockDim.x + threadIdx.x) >> 5;
    int lane = threadIdx.x & 31;
    if (i >= NT) return;
    int side = cfg.pi_side[pi];
    const float* Bn = (side == 0 ? z2n_ : z1n_) + (size_t)cfg.pi_q[pi] * NT * CD;
    const int* idxB = g_idxB + (size_t)pi * NT;
    const int* neighA = g_neighA + (size_t)(side * 4 + cfg.pi_p[pi]) * NT * 5;
    const int* order = g_order + (size_t)pi * NT;
    uint32_t k0 = cfg.kp[pi][0], k1 = cfg.kp[pi][1];
    int ib = idxB[i];
    int uB = ib < 0 ? 0 : ib;
    int nc = g_negc[pi];
    float a[24];
    const float* ar = Bn + (size_t)uB * CD;
#pragma unroll
    for (int u = 0; u < 24; u++) a[u] = ar[lane + u * 32];
    float hs = 0.f; int npos = 0;
    for (int k = 0; k < 5; k++) {
        int pb = idxB[neighA[i * 5 + k]];
        uint32_t bits = tf_bits(k0, k1, 10240u + (uint32_t)(i * 5 + k));
        int nb = order[(int)(bits & 2047u) % nc];
        const float* pr = Bn + (size_t)(pb < 0 ? 0 : pb) * CD;
        const float* nr = Bn + (size_t)nb * CD;
        float dp = 0.f, dn = 0.f;
#pragma unroll
        for (int u = 0; u < 24; u++) {
            dp += a[u] * pr[lane + u * 32];
            dn += a[u] * nr[lane + u * 32];
        }
#pragma unroll
        for (int off = 16; off; off >>= 1) {
            dp += __shfl_xor_sync(0xffffffffu, dp, off);
            dn += __shfl_xor_sync(0xffffffffu, dn, off);
        }
        if (pb >= 0) { hs += fmaxf(dn - dp + 0.4f, 0.f); npos++; }
    }
    if (lane == 0) {
        float per = hs / (float)(npos > 0 ? npos : 1);
        int valid = (ib >= 0) && (npos > 0);
        g_rowNRC[pi * NT + i] = valid ? per : 0.f;
        g_cntNRC[pi * NT + i] = valid ? 1.f : 0.f;
    }
}

// ---------------------------------------------------------------------------
__global__ void reduce_all_kernel() {
    __shared__ float sh[1024];
    int slot = blockIdx.x;
    int t = threadIdx.x;
    const float* buf;
    if (slot < 8) buf = g_rowCB + (size_t)slot * NT;
    else if (slot < 20) buf = g_rowNRC + (size_t)(slot - 8) * NT;
    else buf = g_cntNRC + (size_t)(slot - 20) * NT;
    sh[t] = buf[t] + buf[t + 1024];
    __syncthreads();
    for (int s = 512; s; s >>= 1) {
        if (t < s) sh[t] += sh[t + s];
        __syncthreads();
    }
    if (t == 0) {
        float v = sh[0];
        if (slot < 8) v *= (1.0f / 10240.0f);
        g_slots[slot] = v;
    }
}

__global__ void final_kernel(float* __restrict__ out) {
    float l2 = 0.f;
    for (int i = 0; i < 8; i++) l2 += g_slots[i];
    l2 *= 0.25f;
    float l3 = 0.f;
    for (int s = 0; s < 2; s++) {
        float acc = 0.f;
        for (int j = 0; j < 6; j++) {
            int pi = s * 6 + j;
            float cn = g_slots[20 + pi];
            float sm = g_slots[8 + pi];
            acc += (cn > 0.f) ? sm / fmaxf(cn, 1.f) : 0.f;
        }
        l3 += acc / 6.f;
    }
    out[0] = 10.f * l2 + 10.f * l3;
}

// ---------------------------------------------------------------------------
namespace {
struct HostMT { uint32_t mt[624]; int pos; };
static void mt_seed(HostMT& s, uint32_t seed) {
    for (int p = 0; p < 624; p++) {
        s.mt[p] = seed;
        seed = 1812433253u * (seed ^ (seed >> 30)) + (uint32_t)p + 1u;
    }
    s.pos = 624;
}
static uint32_t mt_next(HostMT& s) {
    if (s.pos == 624) {
        for (int i = 0; i < 624; i++) {
            uint32_t y = (s.mt[i] & 0x80000000u) | (s.mt[(i + 1) % 624] & 0x7fffffffu);
            s.mt[i] = s.mt[(i + 397) % 624] ^ (y >> 1) ^ ((y & 1u) ? 0x9908b0dfu : 0u);
        }
        s.pos = 0;
    }
    uint32_t y = s.mt[s.pos++];
    y ^= y >> 11;
    y ^= (y << 7) & 0x9d2c5680u;
    y ^= (y << 15) & 0xefc60000u;
    y ^= y >> 18;
    return y;
}
static uint32_t mt_interval(HostMT& s, uint32_t mx) {
    if (mx == 0) return 0;
    uint32_t mask = mx;
    mask |= mask >> 1; mask |= mask >> 2; mask |= mask >> 4;
    mask |= mask >> 8; mask |= mask >> 16;
    uint32_t v;
    while ((v = (mt_next(s) & mask)) > mx) {}
    return v;
}
static void perm12(uint32_t seed, int* out) {
    HostMT s; mt_seed(s, seed);
    for (int i = 0; i < 12; i++) out[i] = i;
    for (int i = 11; i > 0; i--) {
        int j = (int)mt_interval(s, (uint32_t)i);
        int t = out[i]; out[i] = out[j]; out[j] = t;
    }
}
}  // namespace

// ---------------------------------------------------------------------------
extern "C" void kernel_launch(void* const* d_in, const int* in_sizes, int n_in,
                              void* d_out, int out_size) {
    const float* z1 = (const float*)d_in[0];
    const float* z2 = (const float*)d_in[1];
    float* out = (float*)d_out;

    float *z1n, *z2n;
    cudaGetSymbolAddress((void**)&z1n, g_z1n);
    cudaGetSymbolAddress((void**)&z2n, g_z2n);

    Cfg cfg;
    uint32_t ck[4][2];
    for (int i = 0; i < 4; i++)
        threefry2x32(0u, 42u, 0u, (uint32_t)i, ck[i][0], ck[i][1]);
    for (int b = 0; b < 4; b++) {
        threefry2x32(ck[0][0], ck[0][1], 0u, (uint32_t)b, cfg.cbk[b][0], cfg.cbk[b][1]);
        threefry2x32(ck[1][0], ck[1][1], 0u, (uint32_t)b, cfg.cbk[4 + b][0], cfg.cbk[4 + b][1]);
    }
    for (int j = 0; j < 6; j++) {
        threefry2x32(ck[2][0], ck[2][1], 0u, (uint32_t)j, cfg.kp[j][0], cfg.kp[j][1]);
        threefry2x32(ck[3][0], ck[3][1], 0u, (uint32_t)j, cfg.kp[6 + j][0], cfg.kp[6 + j][1]);
    }

    int allp[12][2];
    { int t = 0;
      for (int p = 0; p < 4; p++)
          for (int q = 0; q < 4; q++)
              if (p != q) { allp[t][0] = p; allp[t][1] = q; t++; } }
    int pairs[12][2];
    int perm[12];
    perm12(0u, perm);
    for (int j = 0; j < 6; j++) { pairs[j][0] = allp[perm[j]][0]; pairs[j][1] = allp[perm[j]][1]; }
    perm12(1u, perm);
    for (int j = 0; j < 6; j++) { pairs[6 + j][0] = allp[perm[j]][0]; pairs[6 + j][1] = allp[perm[j]][1]; }

    for (int pi = 0; pi < 12; pi++) {
        cfg.pi_side[pi] = pi / 6;
        cfg.pi_p[pi] = pairs[pi][0];
        cfg.pi_q[pi] = pairs[pi][1];
    }
    // unique cross matrices with transpose dedup (side0 (p,q) ~ side1 (q,p))
    int nU = 0;
    bool matched1[12] = {false};
    for (int j0 = 0; j0 < 6; j0++) {
        cfg.u_side[nU] = 0; cfg.u_p[nU] = pairs[j0][0]; cfg.u_q[nU] = pairs[j0][1];
        cfg.pi_uslot[j0] = nU; cfg.pi_swap[j0] = 0;
        for (int j1 = 6; j1 < 12; j1++) {
            if (!matched1[j1] && pairs[j1][0] == pairs[j0][1] && pairs[j1][1] == pairs[j0][0]) {
                cfg.pi_uslot[j1] = nU; cfg.pi_swap[j1] = 1;
                matched1[j1] = true;
                break;
            }
        }
        nU++;
    }
    for (int j1 = 6; j1 < 12; j1++) {
        if (!matched1[j1]) {
            cfg.u_side[nU] = 1; cfg.u_p[nU] = pairs[j1][0]; cfg.u_q[nU] = pairs[j1][1];
            cfg.pi_uslot[j1] = nU; cfg.pi_swap[j1] = 0;
            nU++;
        }
    }
    cfg.nU = nU;

    normalize_kernel<<<2048, 256>>>(z1, z2);
    init_kernel<<<48, 1024>>>();
    gemm_self_kernel<<<dim3(16, 16, 8), 256>>>(z1, z2);
    self_select_kernel<<<dim3(NT, 8), 128>>>();
    cbneg_kernel<<<dim3(NT, 8), 128>>>(cfg);
    cbloss_kernel<<<dim3(256, 8), 256>>>(z1n, z2n);
    gemm_cross_kernel<<<dim3(16, 16, nU), 256>>>(z1n, z2n, cfg);
    mutual_order_kernel<<<12, 256>>>(cfg);
    nrcloss_kernel<<<dim3(256, 12), 256>>>(z1n, z2n, cfg);
    reduce_all_kernel<<<32, 1024>>>();
    final_kernel<<<1, 1>>>(out);
}

// round 11
// speedup vs baseline: 2.5474x; 1.6079x over previous
#include <cuda_runtime.h>
#include <cuda_bf16.h>
#include <cstdint>

#define NT 2048
#define CD 768
#define INFF  __int_as_float(0x7f800000)
#define NINFF __int_as_float(0xff800000)
typedef unsigned long long ull;

// ---------------------------------------------------------------------------
__device__ float g_z1n[4 * NT * CD];
__device__ float g_z2n[4 * NT * CD];
__device__ __nv_bfloat16 g_rh[8 * NT * CD];   // raw hi  (z1 batches 0-3, z2 4-7)
__device__ __nv_bfloat16 g_rl[8 * NT * CD];   // raw lo
__device__ __nv_bfloat16 g_nh[8 * NT * CD];   // normalized hi
__device__ __nv_bfloat16 g_nl[8 * NT * CD];   // normalized lo
__device__ float g_sq[8 * NT];
__device__ float g_inv[8 * NT];
__device__ float g_Sself[8ULL * NT * NT];
__device__ ull   g_rowmin[12 * NT];
__device__ ull   g_colmin[12 * NT];
__device__ int   g_neighCB[8 * NT * 5];
__device__ int   g_negCB[8 * NT * 5];
__device__ int   g_neighA[8 * NT * 5];
__device__ int   g_idxB[12 * NT];
__device__ int   g_order[12 * NT];
__device__ int   g_negc[12];
__device__ float g_rowCB[8 * NT];
__device__ float g_rowNRC[12 * NT];
__device__ float g_cntNRC[12 * NT];
__device__ float g_slots[32];

struct Cfg {
    int nU;
    int u_side[12], u_p[12], u_q[12];
    int pi_uslot[12], pi_swap[12];
    int pi_side[12], pi_p[12], pi_q[12];
    unsigned kp[12][2];
    unsigned cbk[8][2];
};

// ---------------------------------------------------------------------------
__host__ __device__ __forceinline__ void threefry2x32(
    uint32_t k0, uint32_t k1, uint32_t c0, uint32_t c1, uint32_t& o0, uint32_t& o1)
{
    uint32_t ks2 = k0 ^ k1 ^ 0x1BD11BDAu;
    uint32_t x0 = c0 + k0, x1 = c1 + k1;
#define TF_R(r) { x0 += x1; x1 = (x1 << (r)) | (x1 >> (32 - (r))); x1 ^= x0; }
    TF_R(13) TF_R(15) TF_R(26) TF_R(6)
    x0 += k1;  x1 += ks2 + 1u;
    TF_R(17) TF_R(29) TF_R(16) TF_R(24)
    x0 += ks2; x1 += k0 + 2u;
    TF_R(13) TF_R(15) TF_R(26) TF_R(6)
    x0 += k0;  x1 += k1 + 3u;
    TF_R(17) TF_R(29) TF_R(16) TF_R(24)
    x0 += k1;  x1 += ks2 + 4u;
    TF_R(13) TF_R(15) TF_R(26) TF_R(6)
    x0 += ks2; x1 += k0 + 5u;
#undef TF_R
    o0 = x0; o1 = x1;
}
__host__ __device__ __forceinline__ uint32_t tf_bits(uint32_t k0, uint32_t k1, uint32_t idx) {
    uint32_t o0, o1;
    threefry2x32(k0, k1, 0u, idx, o0, o1);
    return o0 ^ o1;
}
__device__ __forceinline__ ull packmin(float v, unsigned idx) {
    unsigned u = __float_as_uint(v);
    u = (u & 0x80000000u) ? ~u : (u | 0x80000000u);
    return ((ull)u << 32) | idx;
}

// ---------------------------------------------------------------------------
// Normalize + bf16 hi/lo splits (raw and normalized). One warp per row.
// ---------------------------------------------------------------------------
__global__ void normalize_kernel(const float* __restrict__ z1,
                                 const float* __restrict__ z2) {
    int gw = (blockIdx.x * blockDim.x + threadIdx.x) >> 5;
    int lane = threadIdx.x & 31;
    if (gw >= 8 * NT) return;
    const float* src;
    float* dst;
    if (gw < 4 * NT) { src = z1 + (size_t)gw * CD; dst = g_z1n + (size_t)gw * CD; }
    else { src = z2 + (size_t)(gw - 4 * NT) * CD; dst = g_z2n + (size_t)(gw - 4 * NT) * CD; }
    __nv_bfloat16* rh = g_rh + (size_t)gw * CD;
    __nv_bfloat16* rl = g_rl + (size_t)gw * CD;
    __nv_bfloat16* nh = g_nh + (size_t)gw * CD;
    __nv_bfloat16* nl = g_nl + (size_t)gw * CD;
    float a[24];
    float s = 0.f;
#pragma unroll
    for (int u = 0; u < 24; u++) { float v = src[lane + u * 32]; a[u] = v; s += v * v; }
#pragma unroll
    for (int off = 16; off; off >>= 1) s += __shfl_xor_sync(0xffffffffu, s, off);
    float inv = rsqrtf(s + 1e-12f);
    if (lane == 0) { g_sq[gw] = s; g_inv[gw] = inv; }
#pragma unroll
    for (int u = 0; u < 24; u++) {
        int c = lane + u * 32;
        float x = a[u];
        __nv_bfloat16 h = __float2bfloat16_rn(x);
        rh[c] = h; rl[c] = __float2bfloat16_rn(x - __bfloat162float(h));
        float xn = x * inv;
        dst[c] = xn;
        __nv_bfloat16 hn = __float2bfloat16_rn(xn);
        nh[c] = hn; nl[c] = __float2bfloat16_rn(xn - __bfloat162float(hn));
    }
}

__global__ void init_kernel() {
    int i = blockIdx.x * blockDim.x + threadIdx.x;
    if (i < 12 * NT) { g_rowmin[i] = ~0ull; g_colmin[i] = ~0ull; }
}

// ---------------------------------------------------------------------------
// bf16x3 HMMA GEMM. 128x128 tile, BK=32, 8 warps (64x32 each).
// mode 0: self (A=B=raw[z]), store dot to g_Sself[z].
// mode 1: cross (normalized), fused row/col argmin of (1-dot).
// smem rows padded to 40 bf16 (80 B) — conflict-free ldmatrix/LDS.
// ---------------------------------------------------------------------------
#define STG 40960   // bytes per stage: 4 bufs * 128 rows * 80 B
__device__ __forceinline__ void mma16816(float* d, const uint32_t* a, const uint32_t* b) {
    asm volatile(
        "mma.sync.aligned.m16n8k16.row.col.f32.bf16.bf16.f32 "
        "{%0,%1,%2,%3}, {%4,%5,%6,%7}, {%8,%9}, {%0,%1,%2,%3};\n"
        : "+f"(d[0]), "+f"(d[1]), "+f"(d[2]), "+f"(d[3])
        : "r"(a[0]), "r"(a[1]), "r"(a[2]), "r"(a[3]), "r"(b[0]), "r"(b[1]));
}
__device__ __forceinline__ void ldsm4(uint32_t* a, uint32_t p) {
    asm volatile("ldmatrix.sync.aligned.m8n8.x4.shared.b16 {%0,%1,%2,%3}, [%4];\n"
                 : "=r"(a[0]), "=r"(a[1]), "=r"(a[2]), "=r"(a[3]) : "r"(p));
}
__device__ __forceinline__ void cpa16(uint32_t dst, const void* src) {
    asm volatile("cp.async.cg.shared.global [%0], [%1], 16;\n" :: "r"(dst), "l"(src) : "memory");
}

__global__ __launch_bounds__(256, 2) void mma_gemm_kernel(
    const __nv_bfloat16* __restrict__ rh, const __nv_bfloat16* __restrict__ rl,
    const __nv_bfloat16* __restrict__ nh, const __nv_bfloat16* __restrict__ nl,
    int mode, Cfg cfg)
{
    extern __shared__ char dsm[];
    uint32_t smb;
    asm("{ .reg .u64 t; cvta.to.shared.u64 t, %1; cvt.u32.u64 %0, t; }" : "=r"(smb) : "l"(dsm));
    int tid = threadIdx.x, wid = tid >> 5, lane = tid & 31;
    int z = blockIdx.z;
    const __nv_bfloat16 *Ah, *Al, *Bh, *Bl;
    if (mode == 0) {
        Ah = rh + (size_t)z * NT * CD; Al = rl + (size_t)z * NT * CD;
        Bh = Ah; Bl = Al;
    } else {
        int sd = cfg.u_side[z];
        size_t po = (size_t)(sd * 4 + cfg.u_p[z]) * NT * CD;
        size_t qo = (size_t)((1 - sd) * 4 + cfg.u_q[z]) * NT * CD;
        Ah = nh + po; Al = nl + po; Bh = nh + qo; Bl = nl + qo;
    }
    int rbase = blockIdx.y * 128, cbase = blockIdx.x * 128;

    // loader mapping: id = tid + i*256 -> buf(0=Ah,1=Al,2=Bh,3=Bl), row, seg
    auto load_stage = [&](int chunk, int st) {
#pragma unroll
        for (int i = 0; i < 8; i++) {
            int id = tid + i * 256;
            int buf = id >> 9, r = (id >> 2) & 127, seg = id & 3;
            const __nv_bfloat16* gp;
            int grow = (buf < 2 ? rbase : cbase) + r;
            gp = (buf == 0 ? Ah : buf == 1 ? Al : buf == 2 ? Bh : Bl)
                 + (size_t)grow * CD + chunk * 32 + seg * 8;
            cpa16(smb + st * STG + buf * 10240 + r * 80 + seg * 16, gp);
        }
        asm volatile("cp.async.commit_group;\n" ::: "memory");
    };

    float acc[4][4][4];
#pragma unroll
    for (int i = 0; i < 4; i++)
#pragma unroll
        for (int j = 0; j < 4; j++)
#pragma unroll
            for (int k = 0; k < 4; k++) acc[i][j][k] = 0.f;

    int wr = wid >> 2, wc = wid & 3;
    int m0 = wr * 64, n0 = wc * 32;

    load_stage(0, 0);
    for (int c = 0; c < 24; c++) {
        int st = c & 1;
        if (c < 23) {
            load_stage(c + 1, st ^ 1);
            asm volatile("cp.async.wait_group 1;\n" ::: "memory");
        } else {
            asm volatile("cp.async.wait_group 0;\n" ::: "memory");
        }
        __syncthreads();
        uint32_t aH = smb + st * STG, aL = aH + 10240;
        uint32_t bH = aH + 20480, bL = aH + 30720;
#pragma unroll
        for (int ks = 0; ks < 2; ks++) {
            uint32_t arow = (uint32_t)((lane & 15)) * 80 + ks * 32 + ((lane >> 4) << 4);
            uint32_t ah[4][4];
#pragma unroll
            for (int mi = 0; mi < 4; mi++)
                ldsm4(ah[mi], aH + (m0 + mi * 16) * 80 + arow);
            uint32_t boff = (uint32_t)(lane >> 2) * 80 + ks * 32 + ((lane & 3) << 2);
            uint32_t bh[4][2], bl[4][2];
#pragma unroll
            for (int nj = 0; nj < 4; nj++) {
                uint32_t o = (n0 + nj * 8) * 80 + boff;
                bh[nj][0] = *(const uint32_t*)(dsm + st * STG + 20480 + o);
                bh[nj][1] = *(const uint32_t*)(dsm + st * STG + 20480 + o + 16);
                bl[nj][0] = *(const uint32_t*)(dsm + st * STG + 30720 + o);
                bl[nj][1] = *(const uint32_t*)(dsm + st * STG + 30720 + o + 16);
            }
#pragma unroll
            for (int mi = 0; mi < 4; mi++)
#pragma unroll
                for (int nj = 0; nj < 4; nj++) {
                    mma16816(acc[mi][nj], ah[mi], bh[nj]);
                    mma16816(acc[mi][nj], ah[mi], bl[nj]);
                }
            uint32_t al[4][4];
#pragma unroll
            for (int mi = 0; mi < 4; mi++)
                ldsm4(al[mi], aL + (m0 + mi * 16) * 80 + arow);
#pragma unroll
            for (int mi = 0; mi < 4; mi++)
#pragma unroll
                for (int nj = 0; nj < 4; nj++)
                    mma16816(acc[mi][nj], al[mi], bh[nj]);
        }
        __syncthreads();
    }

    if (mode == 0) {
        float* S = g_Sself + (size_t)z * NT * NT;
#pragma unroll
        for (int mi = 0; mi < 4; mi++) {
            int row = rbase + m0 + mi * 16 + (lane >> 2);
#pragma unroll
            for (int nj = 0; nj < 4; nj++) {
                int col = cbase + n0 + nj * 8 + 2 * (lane & 3);
                *(float2*)(S + (size_t)row * NT + col) =
                    make_float2(acc[mi][nj][0], acc[mi][nj][1]);
                *(float2*)(S + (size_t)(row + 8) * NT + col) =
                    make_float2(acc[mi][nj][2], acc[mi][nj][3]);
            }
        }
    } else {
        int u = z;
#pragma unroll
        for (int mi = 0; mi < 4; mi++) {
            int row = rbase + m0 + mi * 16 + (lane >> 2);
            ull r0 = ~0ull, r1 = ~0ull;
#pragma unroll
            for (int nj = 0; nj < 4; nj++) {
                int col = cbase + n0 + nj * 8 + 2 * (lane & 3);
                ull k;
                k = packmin(1.f - acc[mi][nj][0], col);     if (k < r0) r0 = k;
                k = packmin(1.f - acc[mi][nj][1], col + 1); if (k < r0) r0 = k;
                k = packmin(1.f - acc[mi][nj][2], col);     if (k < r1) r1 = k;
                k = packmin(1.f - acc[mi][nj][3], col + 1); if (k < r1) r1 = k;
            }
#pragma unroll
            for (int m = 1; m < 4; m <<= 1) {
                ull o0 = __shfl_xor_sync(0xffffffffu, r0, m);
                ull o1 = __shfl_xor_sync(0xffffffffu, r1, m);
                if (o0 < r0) r0 = o0;
                if (o1 < r1) r1 = o1;
            }
            if ((lane & 3) == 0) {
                atomicMin(&g_rowmin[u * NT + row], r0);
                atomicMin(&g_rowmin[u * NT + row + 8], r1);
            }
        }
#pragma unroll
        for (int nj = 0; nj < 4; nj++) {
            int col = cbase + n0 + nj * 8 + 2 * (lane & 3);
            ull c0 = ~0ull, c1 = ~0ull;
#pragma unroll
            for (int mi = 0; mi < 4; mi++) {
                int row = rbase + m0 + mi * 16 + (lane >> 2);
                ull k;
                k = packmin(1.f - acc[mi][nj][0], row);     if (k < c0) c0 = k;
                k = packmin(1.f - acc[mi][nj][2], row + 8); if (k < c0) c0 = k;
                k = packmin(1.f - acc[mi][nj][1], row);     if (k < c1) c1 = k;
                k = packmin(1.f - acc[mi][nj][3], row + 8); if (k < c1) c1 = k;
            }
#pragma unroll
            for (int m = 4; m < 32; m <<= 1) {
                ull o0 = __shfl_xor_sync(0xffffffffu, c0, m);
                ull o1 = __shfl_xor_sync(0xffffffffu, c1, m);
                if (o0 < c0) c0 = o0;
                if (o1 < c1) c1 = o1;
            }
            if ((lane >> 2) == 0) {
                atomicMin(&g_colmin[u * NT + col], c0);
                atomicMin(&g_colmin[u * NT + col + 1], c1);
            }
        }
    }
}

// ---------------------------------------------------------------------------
// Dual-mode self select with packed 64-bit keys. grid (NT, 8), 4 warps.
// ---------------------------------------------------------------------------
__global__ void self_select_kernel() {
    __shared__ ull smA[24], smB[24];
    int row = blockIdx.x, s = blockIdx.y;
    int wid = threadIdx.x >> 5, lane = threadIdx.x & 31;
    const float* sqv = g_sq + (size_t)s * NT;
    const float* invv = g_inv + (size_t)s * NT;
    const float* r = g_Sself + (size_t)s * NT * NT + (size_t)row * NT;
    float msq = sqv[row], minv = invv[row];
    ull kA[6], kB[6];
#pragma unroll
    for (int u = 0; u < 6; u++) { kA[u] = ~0ull; kB[u] = ~0ull; }
    for (int it = 0; it < 4; it++) {
        int j0 = wid * 512 + it * 128 + lane * 4;
        float4 d4 = *(const float4*)(r + j0);
        float4 q4 = *(const float4*)(sqv + j0);
        float4 i4 = *(const float4*)(invv + j0);
        float dd[4] = {d4.x, d4.y, d4.z, d4.w};
        float qq[4] = {q4.x, q4.y, q4.z, q4.w};
        float ii[4] = {i4.x, i4.y, i4.z, i4.w};
#pragma unroll
        for (int c = 0; c < 4; c++) {
            unsigned j = j0 + c;
            ull k0 = packmin(fmaxf(msq + qq[c] - 2.f * dd[c], 0.f), j);
            if (k0 < kA[5]) {
                int pos = 5;
                while (pos > 0 && k0 < kA[pos - 1]) { kA[pos] = kA[pos - 1]; pos--; }
                kA[pos] = k0;
            }
            ull k1 = packmin(1.f - dd[c] * minv * ii[c], j);
            if (k1 < kB[5]) {
                int pos = 5;
                while (pos > 0 && k1 < kB[pos - 1]) { kB[pos] = kB[pos - 1]; pos--; }
                kB[pos] = k1;
            }
        }
    }
    for (int t = 0; t < 6; t++) {
        ull m = kA[0];
#pragma unroll
        for (int off = 16; off; off >>= 1) {
            ull o = __shfl_down_sync(0xffffffffu, m, off);
            if (o < m) m = o;
        }
        m = __shfl_sync(0xffffffffu, m, 0);
        if (kA[0] == m) {
#pragma unroll
            for (int u = 0; u < 5; u++) kA[u] = kA[u + 1];
            kA[5] = ~0ull;
        }
        if (lane == 0) smA[wid * 6 + t] = m;
        ull w = kB[0];
#pragma unroll
        for (int off = 16; off; off >>= 1) {
            ull o = __shfl_down_sync(0xffffffffu, w, off);
            if (o < w) w = o;
        }
        w = __shfl_sync(0xffffffffu, w, 0);
        if (kB[0] == w) {
#pragma unroll
            for (int u = 0; u < 5; u++) kB[u] = kB[u + 1];
            kB[5] = ~0ull;
        }
        if (lane == 0) smB[wid * 6 + t] = w;
    }
    __syncthreads();
    if (wid < 2) {
        ull* sm = wid ? smB : smA;
        int* outp = (wid ? g_neighA : g_neighCB) + (size_t)s * NT * 5 + row * 5;
        ull k = (lane < 24) ? sm[lane] : ~0ull;
        for (int t = 0; t < 6; t++) {
            ull m = k;
#pragma unroll
            for (int off = 16; off; off >>= 1) {
                ull o = __shfl_down_sync(0xffffffffu, m, off);
                if (o < m) m = o;
            }
            m = __shfl_sync(0xffffffffu, m, 0);
            if (k == m) k = ~0ull;
            if (t > 0 && lane == 0) outp[t - 1] = (int)(m & 0xffffffffu);
        }
    }
}

// ---------------------------------------------------------------------------
__global__ void cbneg_kernel(Cfg cfg) {
    __shared__ float sv[20];
    __shared__ int   si[20];
    int row = blockIdx.x, s = blockIdx.y;
    uint32_t k0 = cfg.cbk[s][0], k1 = cfg.cbk[s][1];
    const int* neigh = g_neighCB + (size_t)s * NT * 5;
    int* neg = g_negCB + (size_t)s * NT * 5;
    int wid = threadIdx.x >> 5, lane = threadIdx.x & 31;
    int n0 = neigh[row * 5 + 0], n1 = neigh[row * 5 + 1], n2 = neigh[row * 5 + 2],
        n3 = neigh[row * 5 + 3], n4 = neigh[row * 5 + 4];
    float bv[5]; int bi[5];
#pragma unroll
    for (int u = 0; u < 5; u++) { bv[u] = NINFF; bi[u] = 0x7fffffff; }
    int jend = wid * 512 + 512;
    for (int j = wid * 512 + lane; j < jend; j += 32) {
        if (j == row || j == n0 || j == n1 || j == n2 || j == n3 || j == n4) continue;
        uint32_t bits = tf_bits(k0, k1, (uint32_t)(row * NT + j));
        float v = __uint_as_float((bits >> 9) | 0x3f800000u) - 1.0f;
        if (v > bv[4] || (v == bv[4] && j < bi[4])) {
            int pos = 4;
            while (pos > 0 && (v > bv[pos - 1] || (v == bv[pos - 1] && j < bi[pos - 1]))) {
                bv[pos] = bv[pos - 1]; bi[pos] = bi[pos - 1]; pos--;
            }
            bv[pos] = v; bi[pos] = j;
        }
    }
    for (int t = 0; t < 5; t++) {
        float v = bv[0]; int id = bi[0];
#pragma unroll
        for (int off = 16; off; off >>= 1) {
            float ov = __shfl_down_sync(0xffffffffu, v, off);
            int oi = __shfl_down_sync(0xffffffffu, id, off);
            if (ov > v || (ov == v && oi < id)) { v = ov; id = oi; }
        }
        v = __shfl_sync(0xffffffffu, v, 0);
        id = __shfl_sync(0xffffffffu, id, 0);
        if (bi[0] == id) {
#pragma unroll
            for (int u = 0; u < 4; u++) { bv[u] = bv[u + 1]; bi[u] = bi[u + 1]; }
            bv[4] = NINFF; bi[4] = 0x7fffffff;
        }
        if (lane == 0) { sv[wid * 5 + t] = v; si[wid * 5 + t] = id; }
    }
    __syncthreads();
    if (wid == 0) {
        float v = (lane < 20) ? sv[lane] : NINFF;
        int id = (lane < 20) ? si[lane] : 0x7fffffff;
        for (int t = 0; t < 5; t++) {
            float wv = v; int wi = id;
#pragma unroll
            for (int off = 16; off; off >>= 1) {
                float ov = __shfl_down_sync(0xffffffffu, wv, off);
                int oi = __shfl_down_sync(0xffffffffu, wi, off);
                if (ov > wv || (ov == wv && oi < wi)) { wv = ov; wi = oi; }
            }
            wi = __shfl_sync(0xffffffffu, wi, 0);
            if (id == wi) { v = NINFF; id = 0x7fffffff; }
            if (lane == 0) neg[row * 5 + t] = wi;
        }
    }
}

// ---------------------------------------------------------------------------
__global__ void cbloss_kernel(const float* __restrict__ z1n_,
                              const float* __restrict__ z2n_) {
    int s = blockIdx.y;
    int row = (blockIdx.x * blockDim.x + threadIdx.x) >> 5;
    int lane = threadIdx.x & 31;
    if (row >= NT) return;
    const float* An = (s < 4 ? z2n_ : z1n_) + (size_t)(s & 3) * NT * CD;
    const int* neigh = g_neighCB + (size_t)s * NT * 5;
    const int* neg = g_negCB + (size_t)s * NT * 5;
    float a[24];
    const float* ar = An + (size_t)row * CD;
#pragma unroll
    for (int u = 0; u < 24; u++) a[u] = ar[lane + u * 32];
    float sacc = 0.f;
    for (int k = 0; k < 5; k++) {
        const float* pr = An + (size_t)neigh[row * 5 + k] * CD;
        const float* nr = An + (size_t)neg[row * 5 + k] * CD;
        float dp = 0.f, dn = 0.f;
#pragma unroll
        for (int u = 0; u < 24; u++) {
            dp += a[u] * pr[lane + u * 32];
            dn += a[u] * nr[lane + u * 32];
        }
#pragma unroll
        for (int off = 16; off; off >>= 1) {
            dp += __shfl_xor_sync(0xffffffffu, dp, off);
            dn += __shfl_xor_sync(0xffffffffu, dn, off);
        }
        float sp = fminf(fmaxf(dp, -1.f), 1.f);
        float sn = fminf(fmaxf(dn, -1.f), 1.f);
        sacc += fmaxf(sn - sp + 0.05f, 0.f);
    }
    if (lane == 0) g_rowCB[s * NT + row] = sacc;
}

// ---------------------------------------------------------------------------
__global__ void mutual_order_kernel(Cfg cfg) {
    __shared__ int matchs[NT];
    __shared__ int cnt[256];
    __shared__ int excl[257];
    int pi = blockIdx.x;
    int u = cfg.pi_uslot[pi], sw = cfg.pi_swap[pi];
    const ull* rm = (sw ? g_colmin : g_rowmin) + (size_t)u * NT;
    const ull* cm = (sw ? g_rowmin : g_colmin) + (size_t)u * NT;
    int* idxB = g_idxB + (size_t)pi * NT;
    int* order = g_order + (size_t)pi * NT;
    int t = threadIdx.x;
    for (int i = t; i < NT; i += 256) matchs[i] = 0;
    __syncthreads();
    int base = t * 8;
#pragma unroll
    for (int uu = 0; uu < 8; uu++) {
        int i = base + uu;
        int b = (int)(rm[i] & 0xffffffffu);
        int v = ((int)(cm[b] & 0xffffffffu) == i) ? b : -1;
        idxB[i] = v;
        if (v >= 0) matchs[v] = 1;
    }
    __syncthreads();
    int m[8]; int c = 0;
#pragma unroll
    for (int uu = 0; uu < 8; uu++) { m[uu] = matchs[base + uu]; c += (m[uu] == 0); }
    cnt[t] = c;
    __syncthreads();
    if (t == 0) {
        int s = 0;
        for (int i = 0; i < 256; i++) { excl[i] = s; s += cnt[i]; }
        excl[256] = s;
    }
    __syncthreads();
    int Utot = excl[256];
    int uo = excl[t];
    int mm = base - uo;
#pragma unroll
    for (int x = 0; x < 8; x++) {
        if (m[x] == 0) order[uo++] = base + x;
        else           order[Utot + mm++] = base + x;
    }
    if (t == 0) g_negc[pi] = (Utot > 0) ? Utot : 1;
}

// ---------------------------------------------------------------------------
__global__ void nrcloss_kernel(const float* __restrict__ z1n_,
                               const float* __restrict__ z2n_, Cfg cfg) {
    int pi = blockIdx.y;
    int i = (blockIdx.x * blockDim.x + threadIdx.x) >> 5;
    int lane = threadIdx.x & 31;
    if (i >= NT) return;
    int side = cfg.pi_side[pi];
    const float* Bn = (side == 0 ? z2n_ : z1n_) + (size_t)cfg.pi_q[pi] * NT * CD;
    const int* idxB = g_idxB + (size_t)pi * NT;
    const int* neighA = g_neighA + (size_t)(side * 4 + cfg.pi_p[pi]) * NT * 5;
    const int* order = g_order + (size_t)pi * NT;
    uint32_t k0 = cfg.kp[pi][0], k1 = cfg.kp[pi][1];
    int ib = idxB[i];
    int uB = ib < 0 ? 0 : ib;
    int nc = g_negc[pi];
    float a[24];
    const float* ar = Bn + (size_t)uB * CD;
#pragma unroll
    for (int u = 0; u < 24; u++) a[u] = ar[lane + u * 32];
    float hs = 0.f; int npos = 0;
    for (int k = 0; k < 5; k++) {
        int pb = idxB[neighA[i * 5 + k]];
        uint32_t bits = tf_bits(k0, k1, 10240u + (uint32_t)(i * 5 + k));
        int nb = order[(int)(bits & 2047u) % nc];
        const float* pr = Bn + (size_t)(pb < 0 ? 0 : pb) * CD;
        const float* nr = Bn + (size_t)nb * CD;
        float dp = 0.f, dn = 0.f;
#pragma unroll
        for (int u = 0; u < 24; u++) {
            dp += a[u] * pr[lane + u * 32];
            dn += a[u] * nr[lane + u * 32];
        }
#pragma unroll
        for (int off = 16; off; off >>= 1) {
            dp += __shfl_xor_sync(0xffffffffu, dp, off);
            dn += __shfl_xor_sync(0xffffffffu, dn, off);
        }
        if (pb >= 0) { hs += fmaxf(dn - dp + 0.4f, 0.f); npos++; }
    }
    if (lane == 0) {
        float per = hs / (float)(npos > 0 ? npos : 1);
        int valid = (ib >= 0) && (npos > 0);
        g_rowNRC[pi * NT + i] = valid ? per : 0.f;
        g_cntNRC[pi * NT + i] = valid ? 1.f : 0.f;
    }
}

// ---------------------------------------------------------------------------
__global__ void reduce_all_kernel() {
    __shared__ float sh[1024];
    int slot = blockIdx.x;
    int t = threadIdx.x;
    const float* buf;
    if (slot < 8) buf = g_rowCB + (size_t)slot * NT;
    else if (slot < 20) buf = g_rowNRC + (size_t)(slot - 8) * NT;
    else buf = g_cntNRC + (size_t)(slot - 20) * NT;
    sh[t] = buf[t] + buf[t + 1024];
    __syncthreads();
    for (int s = 512; s; s >>= 1) {
        if (t < s) sh[t] += sh[t + s];
        __syncthreads();
    }
    if (t == 0) {
        float v = sh[0];
        if (slot < 8) v *= (1.0f / 10240.0f);
        g_slots[slot] = v;
    }
}

__global__ void final_kernel(float* __restrict__ out) {
    float l2 = 0.f;
    for (int i = 0; i < 8; i++) l2 += g_slots[i];
    l2 *= 0.25f;
    float l3 = 0.f;
    for (int s = 0; s < 2; s++) {
        float acc = 0.f;
        for (int j = 0; j < 6; j++) {
            int pi = s * 6 + j;
            float cn = g_slots[20 + pi];
            float sm = g_slots[8 + pi];
            acc += (cn > 0.f) ? sm / fmaxf(cn, 1.f) : 0.f;
        }
        l3 += acc / 6.f;
    }
    out[0] = 10.f * l2 + 10.f * l3;
}

// ---------------------------------------------------------------------------
namespace {
struct HostMT { uint32_t mt[624]; int pos; };
static void mt_seed(HostMT& s, uint32_t seed) {
    for (int p = 0; p < 624; p++) {
        s.mt[p] = seed;
        seed = 1812433253u * (seed ^ (seed >> 30)) + (uint32_t)p + 1u;
    }
    s.pos = 624;
}
static uint32_t mt_next(HostMT& s) {
    if (s.pos == 624) {
        for (int i = 0; i < 624; i++) {
            uint32_t y = (s.mt[i] & 0x80000000u) | (s.mt[(i + 1) % 624] & 0x7fffffffu);
            s.mt[i] = s.mt[(i + 397) % 624] ^ (y >> 1) ^ ((y & 1u) ? 0x9908b0dfu : 0u);
        }
        s.pos = 0;
    }
    uint32_t y = s.mt[s.pos++];
    y ^= y >> 11;
    y ^= (y << 7) & 0x9d2c5680u;
    y ^= (y << 15) & 0xefc60000u;
    y ^= y >> 18;
    return y;
}
static uint32_t mt_interval(HostMT& s, uint32_t mx) {
    if (mx == 0) return 0;
    uint32_t mask = mx;
    mask |= mask >> 1; mask |= mask >> 2; mask |= mask >> 4;
    mask |= mask >> 8; mask |= mask >> 16;
    uint32_t v;
    while ((v = (mt_next(s) & mask)) > mx) {}
    return v;
}
static void perm12(uint32_t seed, int* out) {
    HostMT s; mt_seed(s, seed);
    for (int i = 0; i < 12; i++) out[i] = i;
    for (int i = 11; i > 0; i--) {
        int j = (int)mt_interval(s, (uint32_t)i);
        int t = out[i]; out[i] = out[j]; out[j] = t;
    }
}
}  // namespace

// ---------------------------------------------------------------------------
extern "C" void kernel_launch(void* const* d_in, const int* in_sizes, int n_in,
                              void* d_out, int out_size) {
    const float* z1 = (const float*)d_in[0];
    const float* z2 = (const float*)d_in[1];
    float* out = (float*)d_out;

    float *z1n, *z2n;
    __nv_bfloat16 *rh, *rl, *nh, *nl;
    cudaGetSymbolAddress((void**)&z1n, g_z1n);
    cudaGetSymbolAddress((void**)&z2n, g_z2n);
    cudaGetSymbolAddress((void**)&rh, g_rh);
    cudaGetSymbolAddress((void**)&rl, g_rl);
    cudaGetSymbolAddress((void**)&nh, g_nh);
    cudaGetSymbolAddress((void**)&nl, g_nl);

    Cfg cfg;
    uint32_t ck[4][2];
    for (int i = 0; i < 4; i++)
        threefry2x32(0u, 42u, 0u, (uint32_t)i, ck[i][0], ck[i][1]);
    for (int b = 0; b < 4; b++) {
        threefry2x32(ck[0][0], ck[0][1], 0u, (uint32_t)b, cfg.cbk[b][0], cfg.cbk[b][1]);
        threefry2x32(ck[1][0], ck[1][1], 0u, (uint32_t)b, cfg.cbk[4 + b][0], cfg.cbk[4 + b][1]);
    }
    for (int j = 0; j < 6; j++) {
        threefry2x32(ck[2][0], ck[2][1], 0u, (uint32_t)j, cfg.kp[j][0], cfg.kp[j][1]);
        threefry2x32(ck[3][0], ck[3][1], 0u, (uint32_t)j, cfg.kp[6 + j][0], cfg.kp[6 + j][1]);
    }

    int allp[12][2];
    { int t = 0;
      for (int p = 0; p < 4; p++)
          for (int q = 0; q < 4; q++)
              if (p != q) { allp[t][0] = p; allp[t][1] = q; t++; } }
    int pairs[12][2];
    int perm[12];
    perm12(0u, perm);
    for (int j = 0; j < 6; j++) { pairs[j][0] = allp[perm[j]][0]; pairs[j][1] = allp[perm[j]][1]; }
    perm12(1u, perm);
    for (int j = 0; j < 6; j++) { pairs[6 + j][0] = allp[perm[j]][0]; pairs[6 + j][1] = allp[perm[j]][1]; }

    for (int pi = 0; pi < 12; pi++) {
        cfg.pi_side[pi] = pi / 6;
        cfg.pi_p[pi] = pairs[pi][0];
        cfg.pi_q[pi] = pairs[pi][1];
    }
    int nU = 0;
    bool matched1[12] = {false};
    for (int j0 = 0; j0 < 6; j0++) {
        cfg.u_side[nU] = 0; cfg.u_p[nU] = pairs[j0][0]; cfg.u_q[nU] = pairs[j0][1];
        cfg.pi_uslot[j0] = nU; cfg.pi_swap[j0] = 0;
        for (int j1 = 6; j1 < 12; j1++) {
            if (!matched1[j1] && pairs[j1][0] == pairs[j0][1] && pairs[j1][1] == pairs[j0][0]) {
                cfg.pi_uslot[j1] = nU; cfg.pi_swap[j1] = 1;
                matched1[j1] = true;
                break;
            }
        }
        nU++;
    }
    for (int j1 = 6; j1 < 12; j1++) {
        if (!matched1[j1]) {
            cfg.u_side[nU] = 1; cfg.u_p[nU] = pairs[j1][0]; cfg.u_q[nU] = pairs[j1][1];
            cfg.pi_uslot[j1] = nU; cfg.pi_swap[j1] = 0;
            nU++;
        }
    }
    cfg.nU = nU;

    static bool attrSet = false;
    if (!attrSet) {
        cudaFuncSetAttribute(mma_gemm_kernel,
                             cudaFuncAttributeMaxDynamicSharedMemorySize, 2 * STG);
        attrSet = true;
    }

    normalize_kernel<<<2048, 256>>>(z1, z2);
    init_kernel<<<48, 1024>>>();
    mma_gemm_kernel<<<dim3(16, 16, 8), 256, 2 * STG>>>(rh, rl, nh, nl, 0, cfg);
    self_select_kernel<<<dim3(NT, 8), 128>>>();
    cbneg_kernel<<<dim3(NT, 8), 128>>>(cfg);
    cbloss_kernel<<<dim3(256, 8), 256>>>(z1n, z2n);
    mma_gemm_kernel<<<dim3(16, 16, nU), 256, 2 * STG>>>(rh, rl, nh, nl, 1, cfg);
    mutual_order_kernel<<<12, 256>>>(cfg);
    nrcloss_kernel<<<dim3(256, 12), 256>>>(z1n, z2n, cfg);
    reduce_all_kernel<<<32, 1024>>>();
    final_kernel<<<1, 1>>>(out);
}

// round 12
// speedup vs baseline: 2.5795x; 1.0126x over previous
#include <cuda_runtime.h>
#include <cuda_bf16.h>
#include <cstdint>

#define NT 2048
#define CD 768
#define INFF  __int_as_float(0x7f800000)
#define NINFF __int_as_float(0xff800000)
typedef unsigned long long ull;

// ---------------------------------------------------------------------------
__device__ float g_z1n[4 * NT * CD];
__device__ float g_z2n[4 * NT * CD];
__device__ __nv_bfloat16 g_rh[8 * NT * CD];
__device__ __nv_bfloat16 g_rl[8 * NT * CD];
__device__ __nv_bfloat16 g_nh[8 * NT * CD];
__device__ __nv_bfloat16 g_nl[8 * NT * CD];
__device__ float g_sq[8 * NT];
__device__ float g_inv[8 * NT];
__device__ float g_Sself[8ULL * NT * NT];
__device__ ull   g_rowmin[12 * NT];
__device__ ull   g_colmin[12 * NT];
__device__ int   g_neighCB[8 * NT * 5];
__device__ int   g_negCB[8 * NT * 5];
__device__ int   g_neighA[8 * NT * 5];
__device__ int   g_idxB[12 * NT];
__device__ int   g_order[12 * NT];
__device__ int   g_negc[12];
__device__ float g_rowCB[8 * NT];
__device__ float g_rowNRC[12 * NT];
__device__ float g_cntNRC[12 * NT];
__device__ float g_slots[32];

struct Cfg {
    int nU;
    int u_side[12], u_p[12], u_q[12];
    int pi_uslot[12], pi_swap[12];
    int pi_side[12], pi_p[12], pi_q[12];
    unsigned kp[12][2];
    unsigned cbk[8][2];
};

// ---------------------------------------------------------------------------
__host__ __device__ __forceinline__ void threefry2x32(
    uint32_t k0, uint32_t k1, uint32_t c0, uint32_t c1, uint32_t& o0, uint32_t& o1)
{
    uint32_t ks2 = k0 ^ k1 ^ 0x1BD11BDAu;
    uint32_t x0 = c0 + k0, x1 = c1 + k1;
#define TF_R(r) { x0 += x1; x1 = (x1 << (r)) | (x1 >> (32 - (r))); x1 ^= x0; }
    TF_R(13) TF_R(15) TF_R(26) TF_R(6)
    x0 += k1;  x1 += ks2 + 1u;
    TF_R(17) TF_R(29) TF_R(16) TF_R(24)
    x0 += ks2; x1 += k0 + 2u;
    TF_R(13) TF_R(15) TF_R(26) TF_R(6)
    x0 += k0;  x1 += k1 + 3u;
    TF_R(17) TF_R(29) TF_R(16) TF_R(24)
    x0 += k1;  x1 += ks2 + 4u;
    TF_R(13) TF_R(15) TF_R(26) TF_R(6)
    x0 += ks2; x1 += k0 + 5u;
#undef TF_R
    o0 = x0; o1 = x1;
}
__host__ __device__ __forceinline__ uint32_t tf_bits(uint32_t k0, uint32_t k1, uint32_t idx) {
    uint32_t o0, o1;
    threefry2x32(k0, k1, 0u, idx, o0, o1);
    return o0 ^ o1;
}
__device__ __forceinline__ ull packmin(float v, unsigned idx) {
    unsigned u = __float_as_uint(v);
    u = (u & 0x80000000u) ? ~u : (u | 0x80000000u);
    return ((ull)u << 32) | idx;
}
// non-negative floats only: uint bits are monotone
__device__ __forceinline__ ull packnn(float v, unsigned idx) {
    return ((ull)__float_as_uint(v) << 32) | idx;
}

// ---------------------------------------------------------------------------
__global__ void normalize_kernel(const float* __restrict__ z1,
                                 const float* __restrict__ z2) {
    int gw = (blockIdx.x * blockDim.x + threadIdx.x) >> 5;
    int lane = threadIdx.x & 31;
    if (gw >= 8 * NT) return;
    const float* src;
    float* dst;
    if (gw < 4 * NT) { src = z1 + (size_t)gw * CD; dst = g_z1n + (size_t)gw * CD; }
    else { src = z2 + (size_t)(gw - 4 * NT) * CD; dst = g_z2n + (size_t)(gw - 4 * NT) * CD; }
    __nv_bfloat16* rh = g_rh + (size_t)gw * CD;
    __nv_bfloat16* rl = g_rl + (size_t)gw * CD;
    __nv_bfloat16* nh = g_nh + (size_t)gw * CD;
    __nv_bfloat16* nl = g_nl + (size_t)gw * CD;
    float a[24];
    float s = 0.f;
#pragma unroll
    for (int u = 0; u < 24; u++) { float v = src[lane + u * 32]; a[u] = v; s += v * v; }
#pragma unroll
    for (int off = 16; off; off >>= 1) s += __shfl_xor_sync(0xffffffffu, s, off);
    float inv = rsqrtf(s + 1e-12f);
    if (lane == 0) { g_sq[gw] = s; g_inv[gw] = inv; }
#pragma unroll
    for (int u = 0; u < 24; u++) {
        int c = lane + u * 32;
        float x = a[u];
        __nv_bfloat16 h = __float2bfloat16_rn(x);
        rh[c] = h; rl[c] = __float2bfloat16_rn(x - __bfloat162float(h));
        float xn = x * inv;
        dst[c] = xn;
        __nv_bfloat16 hn = __float2bfloat16_rn(xn);
        nh[c] = hn; nl[c] = __float2bfloat16_rn(xn - __bfloat162float(hn));
    }
}

__global__ void init_kernel() {
    int i = blockIdx.x * blockDim.x + threadIdx.x;
    if (i < 12 * NT) { g_rowmin[i] = ~0ull; g_colmin[i] = ~0ull; }
}

// ---------------------------------------------------------------------------
// bf16x3 HMMA GEMM (see R11). mode 0: self -> store S. mode 1: cross -> argmin.
// ---------------------------------------------------------------------------
#define STG 40960
__device__ __forceinline__ void mma16816(float* d, const uint32_t* a, const uint32_t* b) {
    asm volatile(
        "mma.sync.aligned.m16n8k16.row.col.f32.bf16.bf16.f32 "
        "{%0,%1,%2,%3}, {%4,%5,%6,%7}, {%8,%9}, {%0,%1,%2,%3};\n"
        : "+f"(d[0]), "+f"(d[1]), "+f"(d[2]), "+f"(d[3])
        : "r"(a[0]), "r"(a[1]), "r"(a[2]), "r"(a[3]), "r"(b[0]), "r"(b[1]));
}
__device__ __forceinline__ void ldsm4(uint32_t* a, uint32_t p) {
    asm volatile("ldmatrix.sync.aligned.m8n8.x4.shared.b16 {%0,%1,%2,%3}, [%4];\n"
                 : "=r"(a[0]), "=r"(a[1]), "=r"(a[2]), "=r"(a[3]) : "r"(p));
}
__device__ __forceinline__ void cpa16(uint32_t dst, const void* src) {
    asm volatile("cp.async.cg.shared.global [%0], [%1], 16;\n" :: "r"(dst), "l"(src) : "memory");
}

__global__ __launch_bounds__(256, 2) void mma_gemm_kernel(
    const __nv_bfloat16* __restrict__ rh, const __nv_bfloat16* __restrict__ rl,
    const __nv_bfloat16* __restrict__ nh, const __nv_bfloat16* __restrict__ nl,
    int mode, Cfg cfg)
{
    extern __shared__ char dsm[];
    uint32_t smb;
    asm("{ .reg .u64 t; cvta.to.shared.u64 t, %1; cvt.u32.u64 %0, t; }" : "=r"(smb) : "l"(dsm));
    int tid = threadIdx.x, wid = tid >> 5, lane = tid & 31;
    int z = blockIdx.z;
    const __nv_bfloat16 *Ah, *Al, *Bh, *Bl;
    if (mode == 0) {
        Ah = rh + (size_t)z * NT * CD; Al = rl + (size_t)z * NT * CD;
        Bh = Ah; Bl = Al;
    } else {
        int sd = cfg.u_side[z];
        size_t po = (size_t)(sd * 4 + cfg.u_p[z]) * NT * CD;
        size_t qo = (size_t)((1 - sd) * 4 + cfg.u_q[z]) * NT * CD;
        Ah = nh + po; Al = nl + po; Bh = nh + qo; Bl = nl + qo;
    }
    int rbase = blockIdx.y * 128, cbase = blockIdx.x * 128;

    auto load_stage = [&](int chunk, int st) {
#pragma unroll
        for (int i = 0; i < 8; i++) {
            int id = tid + i * 256;
            int buf = id >> 9, r = (id >> 2) & 127, seg = id & 3;
            const __nv_bfloat16* gp;
            int grow = (buf < 2 ? rbase : cbase) + r;
            gp = (buf == 0 ? Ah : buf == 1 ? Al : buf == 2 ? Bh : Bl)
                 + (size_t)grow * CD + chunk * 32 + seg * 8;
            cpa16(smb + st * STG + buf * 10240 + r * 80 + seg * 16, gp);
        }
        asm volatile("cp.async.commit_group;\n" ::: "memory");
    };

    float acc[4][4][4];
#pragma unroll
    for (int i = 0; i < 4; i++)
#pragma unroll
        for (int j = 0; j < 4; j++)
#pragma unroll
            for (int k = 0; k < 4; k++) acc[i][j][k] = 0.f;

    int wr = wid >> 2, wc = wid & 3;
    int m0 = wr * 64, n0 = wc * 32;

    load_stage(0, 0);
    for (int c = 0; c < 24; c++) {
        int st = c & 1;
        if (c < 23) {
            load_stage(c + 1, st ^ 1);
            asm volatile("cp.async.wait_group 1;\n" ::: "memory");
        } else {
            asm volatile("cp.async.wait_group 0;\n" ::: "memory");
        }
        __syncthreads();
        uint32_t aH = smb + st * STG, aL = aH + 10240;
#pragma unroll
        for (int ks = 0; ks < 2; ks++) {
            uint32_t arow = (uint32_t)((lane & 15)) * 80 + ks * 32 + ((lane >> 4) << 4);
            uint32_t ah[4][4];
#pragma unroll
            for (int mi = 0; mi < 4; mi++)
                ldsm4(ah[mi], aH + (m0 + mi * 16) * 80 + arow);
            uint32_t boff = (uint32_t)(lane >> 2) * 80 + ks * 32 + ((lane & 3) << 2);
            uint32_t bh[4][2], bl[4][2];
#pragma unroll
            for (int nj = 0; nj < 4; nj++) {
                uint32_t o = (n0 + nj * 8) * 80 + boff;
                bh[nj][0] = *(const uint32_t*)(dsm + st * STG + 20480 + o);
                bh[nj][1] = *(const uint32_t*)(dsm + st * STG + 20480 + o + 16);
                bl[nj][0] = *(const uint32_t*)(dsm + st * STG + 30720 + o);
                bl[nj][1] = *(const uint32_t*)(dsm + st * STG + 30720 + o + 16);
            }
#pragma unroll
            for (int mi = 0; mi < 4; mi++)
#pragma unroll
                for (int nj = 0; nj < 4; nj++) {
                    mma16816(acc[mi][nj], ah[mi], bh[nj]);
                    mma16816(acc[mi][nj], ah[mi], bl[nj]);
                }
            uint32_t al[4][4];
#pragma unroll
            for (int mi = 0; mi < 4; mi++)
                ldsm4(al[mi], aL + (m0 + mi * 16) * 80 + arow);
#pragma unroll
            for (int mi = 0; mi < 4; mi++)
#pragma unroll
                for (int nj = 0; nj < 4; nj++)
                    mma16816(acc[mi][nj], al[mi], bh[nj]);
        }
        __syncthreads();
    }

    if (mode == 0) {
        float* S = g_Sself + (size_t)z * NT * NT;
#pragma unroll
        for (int mi = 0; mi < 4; mi++) {
            int row = rbase + m0 + mi * 16 + (lane >> 2);
#pragma unroll
            for (int nj = 0; nj < 4; nj++) {
                int col = cbase + n0 + nj * 8 + 2 * (lane & 3);
                *(float2*)(S + (size_t)row * NT + col) =
                    make_float2(acc[mi][nj][0], acc[mi][nj][1]);
                *(float2*)(S + (size_t)(row + 8) * NT + col) =
                    make_float2(acc[mi][nj][2], acc[mi][nj][3]);
            }
        }
    } else {
        int u = z;
#pragma unroll
        for (int mi = 0; mi < 4; mi++) {
            int row = rbase + m0 + mi * 16 + (lane >> 2);
            ull r0 = ~0ull, r1 = ~0ull;
#pragma unroll
            for (int nj = 0; nj < 4; nj++) {
                int col = cbase + n0 + nj * 8 + 2 * (lane & 3);
                ull k;
                k = packmin(1.f - acc[mi][nj][0], col);     if (k < r0) r0 = k;
                k = packmin(1.f - acc[mi][nj][1], col + 1); if (k < r0) r0 = k;
                k = packmin(1.f - acc[mi][nj][2], col);     if (k < r1) r1 = k;
                k = packmin(1.f - acc[mi][nj][3], col + 1); if (k < r1) r1 = k;
            }
#pragma unroll
            for (int m = 1; m < 4; m <<= 1) {
                ull o0 = __shfl_xor_sync(0xffffffffu, r0, m);
                ull o1 = __shfl_xor_sync(0xffffffffu, r1, m);
                if (o0 < r0) r0 = o0;
                if (o1 < r1) r1 = o1;
            }
            if ((lane & 3) == 0) {
                atomicMin(&g_rowmin[u * NT + row], r0);
                atomicMin(&g_rowmin[u * NT + row + 8], r1);
            }
        }
#pragma unroll
        for (int nj = 0; nj < 4; nj++) {
            int col = cbase + n0 + nj * 8 + 2 * (lane & 3);
            ull c0 = ~0ull, c1 = ~0ull;
#pragma unroll
            for (int mi = 0; mi < 4; mi++) {
                int row = rbase + m0 + mi * 16 + (lane >> 2);
                ull k;
                k = packmin(1.f - acc[mi][nj][0], row);     if (k < c0) c0 = k;
                k = packmin(1.f - acc[mi][nj][2], row + 8); if (k < c0) c0 = k;
                k = packmin(1.f - acc[mi][nj][1], row);     if (k < c1) c1 = k;
                k = packmin(1.f - acc[mi][nj][3], row + 8); if (k < c1) c1 = k;
            }
#pragma unroll
            for (int m = 4; m < 32; m <<= 1) {
                ull o0 = __shfl_xor_sync(0xffffffffu, c0, m);
                ull o1 = __shfl_xor_sync(0xffffffffu, c1, m);
                if (o0 < c0) c0 = o0;
                if (o1 < c1) c1 = o1;
            }
            if ((lane >> 2) == 0) {
                atomicMin(&g_colmin[u * NT + col], c0);
                atomicMin(&g_colmin[u * NT + col + 1], c1);
            }
        }
    }
}

// ---------------------------------------------------------------------------
// Dual-mode self select. Prefetched loads, direct non-negative packing.
// ---------------------------------------------------------------------------
__global__ void self_select_kernel() {
    __shared__ ull smA[24], smB[24];
    int row = blockIdx.x, s = blockIdx.y;
    int wid = threadIdx.x >> 5, lane = threadIdx.x & 31;
    const float* sqv = g_sq + (size_t)s * NT;
    const float* invv = g_inv + (size_t)s * NT;
    const float* r = g_Sself + (size_t)s * NT * NT + (size_t)row * NT;
    float msq = sqv[row], minv = invv[row];
    ull kA[6], kB[6];
#pragma unroll
    for (int u = 0; u < 6; u++) { kA[u] = ~0ull; kB[u] = ~0ull; }

    float4 dd[4], qq[4], ii[4];
#pragma unroll
    for (int it = 0; it < 4; it++) {
        int j0 = wid * 512 + it * 128 + lane * 4;
        dd[it] = *(const float4*)(r + j0);
        qq[it] = *(const float4*)(sqv + j0);
        ii[it] = *(const float4*)(invv + j0);
    }
#pragma unroll
    for (int it = 0; it < 4; it++) {
        int j0 = wid * 512 + it * 128 + lane * 4;
        float d_[4] = {dd[it].x, dd[it].y, dd[it].z, dd[it].w};
        float q_[4] = {qq[it].x, qq[it].y, qq[it].z, qq[it].w};
        float i_[4] = {ii[it].x, ii[it].y, ii[it].z, ii[it].w};
#pragma unroll
        for (int c = 0; c < 4; c++) {
            unsigned j = j0 + c;
            float v0 = fmaxf(msq + q_[c] - 2.f * d_[c], 0.f);
            ull k0 = packnn(v0, j);
            if (k0 < kA[5]) {
                int pos = 5;
                while (pos > 0 && k0 < kA[pos - 1]) { kA[pos] = kA[pos - 1]; pos--; }
                kA[pos] = k0;
            }
            float v1 = fmaxf(1.f - d_[c] * minv * i_[c], 0.f);
            ull k1 = packnn(v1, j);
            if (k1 < kB[5]) {
                int pos = 5;
                while (pos > 0 && k1 < kB[pos - 1]) { kB[pos] = kB[pos - 1]; pos--; }
                kB[pos] = k1;
            }
        }
    }
    for (int t = 0; t < 6; t++) {
        ull m = kA[0];
#pragma unroll
        for (int off = 16; off; off >>= 1) {
            ull o = __shfl_down_sync(0xffffffffu, m, off);
            if (o < m) m = o;
        }
        m = __shfl_sync(0xffffffffu, m, 0);
        if (kA[0] == m) {
#pragma unroll
            for (int u = 0; u < 5; u++) kA[u] = kA[u + 1];
            kA[5] = ~0ull;
        }
        if (lane == 0) smA[wid * 6 + t] = m;
        ull w = kB[0];
#pragma unroll
        for (int off = 16; off; off >>= 1) {
            ull o = __shfl_down_sync(0xffffffffu, w, off);
            if (o < w) w = o;
        }
        w = __shfl_sync(0xffffffffu, w, 0);
        if (kB[0] == w) {
#pragma unroll
            for (int u = 0; u < 5; u++) kB[u] = kB[u + 1];
            kB[5] = ~0ull;
        }
        if (lane == 0) smB[wid * 6 + t] = w;
    }
    __syncthreads();
    if (wid < 2) {
        ull* sm = wid ? smB : smA;
        int* outp = (wid ? g_neighA : g_neighCB) + (size_t)s * NT * 5 + row * 5;
        ull k = (lane < 24) ? sm[lane] : ~0ull;
        for (int t = 0; t < 6; t++) {
            ull m = k;
#pragma unroll
            for (int off = 16; off; off >>= 1) {
                ull o = __shfl_down_sync(0xffffffffu, m, off);
                if (o < m) m = o;
            }
            m = __shfl_sync(0xffffffffu, m, 0);
            if (k == m) k = ~0ull;
            if (t > 0 && lane == 0) outp[t - 1] = (int)(m & 0xffffffffu);
        }
    }
}

// ---------------------------------------------------------------------------
// cbneg with packed keys: top-5 largest uniform == min-5 of (0x7fffff - bits>>9).
// ---------------------------------------------------------------------------
__global__ void cbneg_kernel(Cfg cfg) {
    __shared__ ull sm[20];
    int row = blockIdx.x, s = blockIdx.y;
    uint32_t k0 = cfg.cbk[s][0], k1 = cfg.cbk[s][1];
    const int* neigh = g_neighCB + (size_t)s * NT * 5;
    int* neg = g_negCB + (size_t)s * NT * 5;
    int wid = threadIdx.x >> 5, lane = threadIdx.x & 31;
    int n0 = neigh[row * 5 + 0], n1 = neigh[row * 5 + 1], n2 = neigh[row * 5 + 2],
        n3 = neigh[row * 5 + 3], n4 = neigh[row * 5 + 4];
    ull kk[5];
#pragma unroll
    for (int u = 0; u < 5; u++) kk[u] = ~0ull;
    int jend = wid * 512 + 512;
    for (int j = wid * 512 + lane; j < jend; j += 32) {
        if (j == row || j == n0 || j == n1 || j == n2 || j == n3 || j == n4) continue;
        uint32_t bits = tf_bits(k0, k1, (uint32_t)(row * NT + j));
        ull k = ((ull)(0x007fffffu - (bits >> 9)) << 32) | (unsigned)j;
        if (k < kk[4]) {
            int pos = 4;
            while (pos > 0 && k < kk[pos - 1]) { kk[pos] = kk[pos - 1]; pos--; }
            kk[pos] = k;
        }
    }
    for (int t = 0; t < 5; t++) {
        ull m = kk[0];
#pragma unroll
        for (int off = 16; off; off >>= 1) {
            ull o = __shfl_down_sync(0xffffffffu, m, off);
            if (o < m) m = o;
        }
        m = __shfl_sync(0xffffffffu, m, 0);
        if (kk[0] == m) {
#pragma unroll
            for (int u = 0; u < 4; u++) kk[u] = kk[u + 1];
            kk[4] = ~0ull;
        }
        if (lane == 0) sm[wid * 5 + t] = m;
    }
    __syncthreads();
    if (wid == 0) {
        ull k = (lane < 20) ? sm[lane] : ~0ull;
        for (int t = 0; t < 5; t++) {
            ull m = k;
#pragma unroll
            for (int off = 16; off; off >>= 1) {
                ull o = __shfl_down_sync(0xffffffffu, m, off);
                if (o < m) m = o;
            }
            m = __shfl_sync(0xffffffffu, m, 0);
            if (k == m) k = ~0ull;
            if (lane == 0) neg[row * 5 + t] = (int)(m & 0xffffffffu);
        }
    }
}

// ---------------------------------------------------------------------------
__global__ void cbloss_kernel(const float* __restrict__ z1n_,
                              const float* __restrict__ z2n_) {
    int s = blockIdx.y;
    int row = (blockIdx.x * blockDim.x + threadIdx.x) >> 5;
    int lane = threadIdx.x & 31;
    if (row >= NT) return;
    const float* An = (s < 4 ? z2n_ : z1n_) + (size_t)(s & 3) * NT * CD;
    const int* neigh = g_neighCB + (size_t)s * NT * 5;
    const int* neg = g_negCB + (size_t)s * NT * 5;
    float a[24];
    const float* ar = An + (size_t)row * CD;
#pragma unroll
    for (int u = 0; u < 24; u++) a[u] = ar[lane + u * 32];
    float sacc = 0.f;
    for (int k = 0; k < 5; k++) {
        const float* pr = An + (size_t)neigh[row * 5 + k] * CD;
        const float* nr = An + (size_t)neg[row * 5 + k] * CD;
        float dp = 0.f, dn = 0.f;
#pragma unroll
        for (int u = 0; u < 24; u++) {
            dp += a[u] * pr[lane + u * 32];
            dn += a[u] * nr[lane + u * 32];
        }
#pragma unroll
        for (int off = 16; off; off >>= 1) {
            dp += __shfl_xor_sync(0xffffffffu, dp, off);
            dn += __shfl_xor_sync(0xffffffffu, dn, off);
        }
        float sp = fminf(fmaxf(dp, -1.f), 1.f);
        float sn = fminf(fmaxf(dn, -1.f), 1.f);
        sacc += fmaxf(sn - sp + 0.05f, 0.f);
    }
    if (lane == 0) g_rowCB[s * NT + row] = sacc;
}

// ---------------------------------------------------------------------------
__global__ void mutual_order_kernel(Cfg cfg) {
    __shared__ int matchs[NT];
    __shared__ int cnt[256];
    __shared__ int excl[257];
    int pi = blockIdx.x;
    int u = cfg.pi_uslot[pi], sw = cfg.pi_swap[pi];
    const ull* rm = (sw ? g_colmin : g_rowmin) + (size_t)u * NT;
    const ull* cm = (sw ? g_rowmin : g_colmin) + (size_t)u * NT;
    int* idxB = g_idxB + (size_t)pi * NT;
    int* order = g_order + (size_t)pi * NT;
    int t = threadIdx.x;
    for (int i = t; i < NT; i += 256) matchs[i] = 0;
    __syncthreads();
    int base = t * 8;
#pragma unroll
    for (int uu = 0; uu < 8; uu++) {
        int i = base + uu;
        int b = (int)(rm[i] & 0xffffffffu);
        int v = ((int)(cm[b] & 0xffffffffu) == i) ? b : -1;
        idxB[i] = v;
        if (v >= 0) matchs[v] = 1;
    }
    __syncthreads();
    int m[8]; int c = 0;
#pragma unroll
    for (int uu = 0; uu < 8; uu++) { m[uu] = matchs[base + uu]; c += (m[uu] == 0); }
    cnt[t] = c;
    __syncthreads();
    if (t == 0) {
        int s = 0;
        for (int i = 0; i < 256; i++) { excl[i] = s; s += cnt[i]; }
        excl[256] = s;
    }
    __syncthreads();
    int Utot = excl[256];
    int uo = excl[t];
    int mm = base - uo;
#pragma unroll
    for (int x = 0; x < 8; x++) {
        if (m[x] == 0) order[uo++] = base + x;
        else           order[Utot + mm++] = base + x;
    }
    if (t == 0) g_negc[pi] = (Utot > 0) ? Utot : 1;
}

// ---------------------------------------------------------------------------
__global__ void nrcloss_kernel(const float* __restrict__ z1n_,
                               const float* __restrict__ z2n_, Cfg cfg) {
    int pi = blockIdx.y;
    int i = (blockIdx.x * blockDim.x + threadIdx.x) >> 5;
    int lane = threadIdx.x & 31;
    if (i >= NT) return;
    int side = cfg.pi_side[pi];
    const float* Bn = (side == 0 ? z2n_ : z1n_) + (size_t)cfg.pi_q[pi] * NT * CD;
    const int* idxB = g_idxB + (size_t)pi * NT;
    const int* neighA = g_neighA + (size_t)(side * 4 + cfg.pi_p[pi]) * NT * 5;
    const int* order = g_order + (size_t)pi * NT;
    uint32_t k0 = cfg.kp[pi][0], k1 = cfg.kp[pi][1];
    int ib = idxB[i];
    int uB = ib < 0 ? 0 : ib;
    int nc = g_negc[pi];
    float a[24];
    const float* ar = Bn + (size_t)uB * CD;
#pragma unroll
    for (int u = 0; u < 24; u++) a[u] = ar[lane + u * 32];
    float hs = 0.f; int npos = 0;
    for (int k = 0; k < 5; k++) {
        int pb = idxB[neighA[i * 5 + k]];
        uint32_t bits = tf_bits(k0, k1, 10240u + (uint32_t)(i * 5 + k));
        int nb = order[(int)(bits & 2047u) % nc];
        const float* pr = Bn + (size_t)(pb < 0 ? 0 : pb) * CD;
        const float* nr = Bn + (size_t)nb * CD;
        float dp = 0.f, dn = 0.f;
#pragma unroll
        for (int u = 0; u < 24; u++) {
            dp += a[u] * pr[lane + u * 32];
            dn += a[u] * nr[lane + u * 32];
        }
#pragma unroll
        for (int off = 16; off; off >>= 1) {
            dp += __shfl_xor_sync(0xffffffffu, dp, off);
            dn += __shfl_xor_sync(0xffffffffu, dn, off);
        }
        if (pb >= 0) { hs += fmaxf(dn - dp + 0.4f, 0.f); npos++; }
    }
    if (lane == 0) {
        float per = hs / (float)(npos > 0 ? npos : 1);
        int valid = (ib >= 0) && (npos > 0);
        g_rowNRC[pi * NT + i] = valid ? per : 0.f;
        g_cntNRC[pi * NT + i] = valid ? 1.f : 0.f;
    }
}

// ---------------------------------------------------------------------------
__global__ void reduce_all_kernel() {
    __shared__ float sh[1024];
    int slot = blockIdx.x;
    int t = threadIdx.x;
    const float* buf;
    if (slot < 8) buf = g_rowCB + (size_t)slot * NT;
    else if (slot < 20) buf = g_rowNRC + (size_t)(slot - 8) * NT;
    else buf = g_cntNRC + (size_t)(slot - 20) * NT;
    sh[t] = buf[t] + buf[t + 1024];
    __syncthreads();
    for (int s = 512; s; s >>= 1) {
        if (t < s) sh[t] += sh[t + s];
        __syncthreads();
    }
    if (t == 0) {
        float v = sh[0];
        if (slot < 8) v *= (1.0f / 10240.0f);
        g_slots[slot] = v;
    }
}

__global__ void final_kernel(float* __restrict__ out) {
    float l2 = 0.f;
    for (int i = 0; i < 8; i++) l2 += g_slots[i];
    l2 *= 0.25f;
    float l3 = 0.f;
    for (int s = 0; s < 2; s++) {
        float acc = 0.f;
        for (int j = 0; j < 6; j++) {
            int pi = s * 6 + j;
            float cn = g_slots[20 + pi];
            float sm = g_slots[8 + pi];
            acc += (cn > 0.f) ? sm / fmaxf(cn, 1.f) : 0.f;
        }
        l3 += acc / 6.f;
    }
    out[0] = 10.f * l2 + 10.f * l3;
}

// ---------------------------------------------------------------------------
namespace {
struct HostMT { uint32_t mt[624]; int pos; };
static void mt_seed(HostMT& s, uint32_t seed) {
    for (int p = 0; p < 624; p++) {
        s.mt[p] = seed;
        seed = 1812433253u * (seed ^ (seed >> 30)) + (uint32_t)p + 1u;
    }
    s.pos = 624;
}
static uint32_t mt_next(HostMT& s) {
    if (s.pos == 624) {
        for (int i = 0; i < 624; i++) {
            uint32_t y = (s.mt[i] & 0x80000000u) | (s.mt[(i + 1) % 624] & 0x7fffffffu);
            s.mt[i] = s.mt[(i + 397) % 624] ^ (y >> 1) ^ ((y & 1u) ? 0x9908b0dfu : 0u);
        }
        s.pos = 0;
    }
    uint32_t y = s.mt[s.pos++];
    y ^= y >> 11;
    y ^= (y << 7) & 0x9d2c5680u;
    y ^= (y << 15) & 0xefc60000u;
    y ^= y >> 18;
    return y;
}
static uint32_t mt_interval(HostMT& s, uint32_t mx) {
    if (mx == 0) return 0;
    uint32_t mask = mx;
    mask |= mask >> 1; mask |= mask >> 2; mask |= mask >> 4;
    mask |= mask >> 8; mask |= mask >> 16;
    uint32_t v;
    while ((v = (mt_next(s) & mask)) > mx) {}
    return v;
}
static void perm12(uint32_t seed, int* out) {
    HostMT s; mt_seed(s, seed);
    for (int i = 0; i < 12; i++) out[i] = i;
    for (int i = 11; i > 0; i--) {
        int j = (int)mt_interval(s, (uint32_t)i);
        int t = out[i]; out[i] = out[j]; out[j] = t;
    }
}
}  // namespace

// ---------------------------------------------------------------------------
extern "C" void kernel_launch(void* const* d_in, const int* in_sizes, int n_in,
                              void* d_out, int out_size) {
    const float* z1 = (const float*)d_in[0];
    const float* z2 = (const float*)d_in[1];
    float* out = (float*)d_out;

    float *z1n, *z2n;
    __nv_bfloat16 *rh, *rl, *nh, *nl;
    cudaGetSymbolAddress((void**)&z1n, g_z1n);
    cudaGetSymbolAddress((void**)&z2n, g_z2n);
    cudaGetSymbolAddress((void**)&rh, g_rh);
    cudaGetSymbolAddress((void**)&rl, g_rl);
    cudaGetSymbolAddress((void**)&nh, g_nh);
    cudaGetSymbolAddress((void**)&nl, g_nl);

    Cfg cfg;
    uint32_t ck[4][2];
    for (int i = 0; i < 4; i++)
        threefry2x32(0u, 42u, 0u, (uint32_t)i, ck[i][0], ck[i][1]);
    for (int b = 0; b < 4; b++) {
        threefry2x32(ck[0][0], ck[0][1], 0u, (uint32_t)b, cfg.cbk[b][0], cfg.cbk[b][1]);
        threefry2x32(ck[1][0], ck[1][1], 0u, (uint32_t)b, cfg.cbk[4 + b][0], cfg.cbk[4 + b][1]);
    }
    for (int j = 0; j < 6; j++) {
        threefry2x32(ck[2][0], ck[2][1], 0u, (uint32_t)j, cfg.kp[j][0], cfg.kp[j][1]);
        threefry2x32(ck[3][0], ck[3][1], 0u, (uint32_t)j, cfg.kp[6 + j][0], cfg.kp[6 + j][1]);
    }

    int allp[12][2];
    { int t = 0;
      for (int p = 0; p < 4; p++)
          for (int q = 0; q < 4; q++)
              if (p != q) { allp[t][0] = p; allp[t][1] = q; t++; } }
    int pairs[12][2];
    int perm[12];
    perm12(0u, perm);
    for (int j = 0; j < 6; j++) { pairs[j][0] = allp[perm[j]][0]; pairs[j][1] = allp[perm[j]][1]; }
    perm12(1u, perm);
    for (int j = 0; j < 6; j++) { pairs[6 + j][0] = allp[perm[j]][0]; pairs[6 + j][1] = allp[perm[j]][1]; }

    for (int pi = 0; pi < 12; pi++) {
        cfg.pi_side[pi] = pi / 6;
        cfg.pi_p[pi] = pairs[pi][0];
        cfg.pi_q[pi] = pairs[pi][1];
    }
    int nU = 0;
    bool matched1[12] = {false};
    for (int j0 = 0; j0 < 6; j0++) {
        cfg.u_side[nU] = 0; cfg.u_p[nU] = pairs[j0][0]; cfg.u_q[nU] = pairs[j0][1];
        cfg.pi_uslot[j0] = nU; cfg.pi_swap[j0] = 0;
        for (int j1 = 6; j1 < 12; j1++) {
            if (!matched1[j1] && pairs[j1][0] == pairs[j0][1] && pairs[j1][1] == pairs[j0][0]) {
                cfg.pi_uslot[j1] = nU; cfg.pi_swap[j1] = 1;
                matched1[j1] = true;
                break;
            }
        }
        nU++;
    }
    for (int j1 = 6; j1 < 12; j1++) {
        if (!matched1[j1]) {
            cfg.u_side[nU] = 1; cfg.u_p[nU] = pairs[j1][0]; cfg.u_q[nU] = pairs[j1][1];
            cfg.pi_uslot[j1] = nU; cfg.pi_swap[j1] = 0;
            nU++;
        }
    }
    cfg.nU = nU;

    static cudaStream_t s1 = nullptr;
    static cudaEvent_t evF = nullptr, evJ = nullptr;
    static bool attrSet = false;
    if (!attrSet) {
        cudaFuncSetAttribute(mma_gemm_kernel,
                             cudaFuncAttributeMaxDynamicSharedMemorySize, 2 * STG);
        cudaStreamCreateWithFlags(&s1, cudaStreamNonBlocking);
        cudaEventCreateWithFlags(&evF, cudaEventDisableTiming);
        cudaEventCreateWithFlags(&evJ, cudaEventDisableTiming);
        attrSet = true;
    }

    // Stream 0: normalize + init, then fork.
    normalize_kernel<<<2048, 256>>>(z1, z2);
    init_kernel<<<48, 1024>>>();
    cudaEventRecord(evF, 0);
    cudaStreamWaitEvent(s1, evF, 0);

    // Branch 1 (s1): cross GEMM + fused argmin -> mutual matching.
    mma_gemm_kernel<<<dim3(16, 16, nU), 256, 2 * STG, s1>>>(rh, rl, nh, nl, 1, cfg);
    mutual_order_kernel<<<12, 256, 0, s1>>>(cfg);
    cudaEventRecord(evJ, s1);

    // Branch 0 (default): self GEMM -> select -> crossbrain chain.
    mma_gemm_kernel<<<dim3(16, 16, 8), 256, 2 * STG>>>(rh, rl, nh, nl, 0, cfg);
    self_select_kernel<<<dim3(NT, 8), 128>>>();
    cbneg_kernel<<<dim3(NT, 8), 128>>>(cfg);
    cbloss_kernel<<<dim3(256, 8), 256>>>(z1n, z2n);

    // Join, then NRC losses + reductions.
    cudaStreamWaitEvent(0, evJ, 0);
    nrcloss_kernel<<<dim3(256, 12), 256>>>(z1n, z2n, cfg);
    reduce_all_kernel<<<32, 1024>>>();
    final_kernel<<<1, 1>>>(out);
}

// round 13
// speedup vs baseline: 2.7919x; 1.0823x over previous
#include <cuda_runtime.h>
#include <cuda_bf16.h>
#include <cstdint>

#define NT 2048
#define CD 768
#define INFF  __int_as_float(0x7f800000)
#define NINFF __int_as_float(0xff800000)
typedef unsigned long long ull;

// ---------------------------------------------------------------------------
__device__ float g_z1n[4 * NT * CD];
__device__ float g_z2n[4 * NT * CD];
__device__ __nv_bfloat16 g_rh[8 * NT * CD];
__device__ __nv_bfloat16 g_rl[8 * NT * CD];
__device__ __nv_bfloat16 g_nh[8 * NT * CD];
__device__ __nv_bfloat16 g_nl[8 * NT * CD];
__device__ float g_sq[8 * NT];
__device__ float g_inv[8 * NT];
__device__ float g_Sself[8ULL * NT * NT];
__device__ ull   g_rowmin[12 * NT];
__device__ ull   g_colmin[12 * NT];
__device__ int   g_neighCB[8 * NT * 5];
__device__ int   g_negCB[8 * NT * 5];
__device__ int   g_neighA[8 * NT * 5];
__device__ int   g_idxB[12 * NT];
__device__ int   g_order[12 * NT];
__device__ int   g_negc[12];
__device__ float g_rowCB[8 * NT];
__device__ float g_rowNRC[12 * NT];
__device__ float g_cntNRC[12 * NT];
__device__ float g_slots[32];

struct Cfg {
    int nU;
    int u_side[12], u_p[12], u_q[12];
    int pi_uslot[12], pi_swap[12];
    int pi_side[12], pi_p[12], pi_q[12];
    unsigned kp[12][2];
    unsigned cbk[8][2];
};

// ---------------------------------------------------------------------------
__host__ __device__ __forceinline__ void threefry2x32(
    uint32_t k0, uint32_t k1, uint32_t c0, uint32_t c1, uint32_t& o0, uint32_t& o1)
{
    uint32_t ks2 = k0 ^ k1 ^ 0x1BD11BDAu;
    uint32_t x0 = c0 + k0, x1 = c1 + k1;
#define TF_R(r) { x0 += x1; x1 = (x1 << (r)) | (x1 >> (32 - (r))); x1 ^= x0; }
    TF_R(13) TF_R(15) TF_R(26) TF_R(6)
    x0 += k1;  x1 += ks2 + 1u;
    TF_R(17) TF_R(29) TF_R(16) TF_R(24)
    x0 += ks2; x1 += k0 + 2u;
    TF_R(13) TF_R(15) TF_R(26) TF_R(6)
    x0 += k0;  x1 += k1 + 3u;
    TF_R(17) TF_R(29) TF_R(16) TF_R(24)
    x0 += k1;  x1 += ks2 + 4u;
    TF_R(13) TF_R(15) TF_R(26) TF_R(6)
    x0 += ks2; x1 += k0 + 5u;
#undef TF_R
    o0 = x0; o1 = x1;
}
__host__ __device__ __forceinline__ uint32_t tf_bits(uint32_t k0, uint32_t k1, uint32_t idx) {
    uint32_t o0, o1;
    threefry2x32(k0, k1, 0u, idx, o0, o1);
    return o0 ^ o1;
}
__device__ __forceinline__ ull packmin(float v, unsigned idx) {
    unsigned u = __float_as_uint(v);
    u = (u & 0x80000000u) ? ~u : (u | 0x80000000u);
    return ((ull)u << 32) | idx;
}
__device__ __forceinline__ ull packnn(float v, unsigned idx) {
    return ((ull)__float_as_uint(v) << 32) | idx;
}

// ---------------------------------------------------------------------------
__global__ void normalize_kernel(const float* __restrict__ z1,
                                 const float* __restrict__ z2) {
    int gw = (blockIdx.x * blockDim.x + threadIdx.x) >> 5;
    int lane = threadIdx.x & 31;
    if (gw >= 8 * NT) return;
    const float* src;
    float* dst;
    if (gw < 4 * NT) { src = z1 + (size_t)gw * CD; dst = g_z1n + (size_t)gw * CD; }
    else { src = z2 + (size_t)(gw - 4 * NT) * CD; dst = g_z2n + (size_t)(gw - 4 * NT) * CD; }
    __nv_bfloat16* rh = g_rh + (size_t)gw * CD;
    __nv_bfloat16* rl = g_rl + (size_t)gw * CD;
    __nv_bfloat16* nh = g_nh + (size_t)gw * CD;
    __nv_bfloat16* nl = g_nl + (size_t)gw * CD;
    float a[24];
    float s = 0.f;
#pragma unroll
    for (int u = 0; u < 24; u++) { float v = src[lane + u * 32]; a[u] = v; s += v * v; }
#pragma unroll
    for (int off = 16; off; off >>= 1) s += __shfl_xor_sync(0xffffffffu, s, off);
    float inv = rsqrtf(s + 1e-12f);
    if (lane == 0) { g_sq[gw] = s; g_inv[gw] = inv; }
#pragma unroll
    for (int u = 0; u < 24; u++) {
        int c = lane + u * 32;
        float x = a[u];
        __nv_bfloat16 h = __float2bfloat16_rn(x);
        rh[c] = h; rl[c] = __float2bfloat16_rn(x - __bfloat162float(h));
        float xn = x * inv;
        dst[c] = xn;
        __nv_bfloat16 hn = __float2bfloat16_rn(xn);
        nh[c] = hn; nl[c] = __float2bfloat16_rn(xn - __bfloat162float(hn));
    }
}

__global__ void init_kernel() {
    int i = blockIdx.x * blockDim.x + threadIdx.x;
    if (i < 12 * NT) { g_rowmin[i] = ~0ull; g_colmin[i] = ~0ull; }
}

// ---------------------------------------------------------------------------
// bf16x3 HMMA GEMM. mode 0: self, symmetric (skip bx<by, mirror via smem).
// mode 1: cross, fused row/col argmin of (1-dot).
// ---------------------------------------------------------------------------
#define STG 40960
__device__ __forceinline__ void mma16816(float* d, const uint32_t* a, const uint32_t* b) {
    asm volatile(
        "mma.sync.aligned.m16n8k16.row.col.f32.bf16.bf16.f32 "
        "{%0,%1,%2,%3}, {%4,%5,%6,%7}, {%8,%9}, {%0,%1,%2,%3};\n"
        : "+f"(d[0]), "+f"(d[1]), "+f"(d[2]), "+f"(d[3])
        : "r"(a[0]), "r"(a[1]), "r"(a[2]), "r"(a[3]), "r"(b[0]), "r"(b[1]));
}
__device__ __forceinline__ void ldsm4(uint32_t* a, uint32_t p) {
    asm volatile("ldmatrix.sync.aligned.m8n8.x4.shared.b16 {%0,%1,%2,%3}, [%4];\n"
                 : "=r"(a[0]), "=r"(a[1]), "=r"(a[2]), "=r"(a[3]) : "r"(p));
}
__device__ __forceinline__ void cpa16(uint32_t dst, const void* src) {
    asm volatile("cp.async.cg.shared.global [%0], [%1], 16;\n" :: "r"(dst), "l"(src) : "memory");
}

__global__ __launch_bounds__(256, 2) void mma_gemm_kernel(
    const __nv_bfloat16* __restrict__ rh, const __nv_bfloat16* __restrict__ rl,
    const __nv_bfloat16* __restrict__ nh, const __nv_bfloat16* __restrict__ nl,
    int mode, Cfg cfg)
{
    if (mode == 0 && blockIdx.x < blockIdx.y) return;
    extern __shared__ char dsm[];
    uint32_t smb;
    asm("{ .reg .u64 t; cvta.to.shared.u64 t, %1; cvt.u32.u64 %0, t; }" : "=r"(smb) : "l"(dsm));
    int tid = threadIdx.x, wid = tid >> 5, lane = tid & 31;
    int z = blockIdx.z;
    const __nv_bfloat16 *Ah, *Al, *Bh, *Bl;
    if (mode == 0) {
        Ah = rh + (size_t)z * NT * CD; Al = rl + (size_t)z * NT * CD;
        Bh = Ah; Bl = Al;
    } else {
        int sd = cfg.u_side[z];
        size_t po = (size_t)(sd * 4 + cfg.u_p[z]) * NT * CD;
        size_t qo = (size_t)((1 - sd) * 4 + cfg.u_q[z]) * NT * CD;
        Ah = nh + po; Al = nl + po; Bh = nh + qo; Bl = nl + qo;
    }
    int rbase = blockIdx.y * 128, cbase = blockIdx.x * 128;

    auto load_stage = [&](int chunk, int st) {
#pragma unroll
        for (int i = 0; i < 8; i++) {
            int id = tid + i * 256;
            int buf = id >> 9, r = (id >> 2) & 127, seg = id & 3;
            const __nv_bfloat16* gp;
            int grow = (buf < 2 ? rbase : cbase) + r;
            gp = (buf == 0 ? Ah : buf == 1 ? Al : buf == 2 ? Bh : Bl)
                 + (size_t)grow * CD + chunk * 32 + seg * 8;
            cpa16(smb + st * STG + buf * 10240 + r * 80 + seg * 16, gp);
        }
        asm volatile("cp.async.commit_group;\n" ::: "memory");
    };

    float acc[4][4][4];
#pragma unroll
    for (int i = 0; i < 4; i++)
#pragma unroll
        for (int j = 0; j < 4; j++)
#pragma unroll
            for (int k = 0; k < 4; k++) acc[i][j][k] = 0.f;

    int wr = wid >> 2, wc = wid & 3;
    int m0 = wr * 64, n0 = wc * 32;

    load_stage(0, 0);
    for (int c = 0; c < 24; c++) {
        int st = c & 1;
        if (c < 23) {
            load_stage(c + 1, st ^ 1);
            asm volatile("cp.async.wait_group 1;\n" ::: "memory");
        } else {
            asm volatile("cp.async.wait_group 0;\n" ::: "memory");
        }
        __syncthreads();
        uint32_t aH = smb + st * STG, aL = aH + 10240;
#pragma unroll
        for (int ks = 0; ks < 2; ks++) {
            uint32_t arow = (uint32_t)((lane & 15)) * 80 + ks * 32 + ((lane >> 4) << 4);
            uint32_t ah[4][4];
#pragma unroll
            for (int mi = 0; mi < 4; mi++)
                ldsm4(ah[mi], aH + (m0 + mi * 16) * 80 + arow);
            uint32_t boff = (uint32_t)(lane >> 2) * 80 + ks * 32 + ((lane & 3) << 2);
            uint32_t bh[4][2], bl[4][2];
#pragma unroll
            for (int nj = 0; nj < 4; nj++) {
                uint32_t o = (n0 + nj * 8) * 80 + boff;
                bh[nj][0] = *(const uint32_t*)(dsm + st * STG + 20480 + o);
                bh[nj][1] = *(const uint32_t*)(dsm + st * STG + 20480 + o + 16);
                bl[nj][0] = *(const uint32_t*)(dsm + st * STG + 30720 + o);
                bl[nj][1] = *(const uint32_t*)(dsm + st * STG + 30720 + o + 16);
            }
#pragma unroll
            for (int mi = 0; mi < 4; mi++)
#pragma unroll
                for (int nj = 0; nj < 4; nj++) {
                    mma16816(acc[mi][nj], ah[mi], bh[nj]);
                    mma16816(acc[mi][nj], ah[mi], bl[nj]);
                }
            uint32_t al[4][4];
#pragma unroll
            for (int mi = 0; mi < 4; mi++)
                ldsm4(al[mi], aL + (m0 + mi * 16) * 80 + arow);
#pragma unroll
            for (int mi = 0; mi < 4; mi++)
#pragma unroll
                for (int nj = 0; nj < 4; nj++)
                    mma16816(acc[mi][nj], al[mi], bh[nj]);
        }
        __syncthreads();
    }

    if (mode == 0) {
        float* S = g_Sself + (size_t)z * NT * NT;
#pragma unroll
        for (int mi = 0; mi < 4; mi++) {
            int row = rbase + m0 + mi * 16 + (lane >> 2);
#pragma unroll
            for (int nj = 0; nj < 4; nj++) {
                int col = cbase + n0 + nj * 8 + 2 * (lane & 3);
                *(float2*)(S + (size_t)row * NT + col) =
                    make_float2(acc[mi][nj][0], acc[mi][nj][1]);
                *(float2*)(S + (size_t)(row + 8) * NT + col) =
                    make_float2(acc[mi][nj][2], acc[mi][nj][3]);
            }
        }
        if (blockIdx.x != blockIdx.y) {
            // transpose via padded smem stage (132-float rows, conflict-free)
            float* stage = (float*)dsm;
#pragma unroll
            for (int mi = 0; mi < 4; mi++) {
                int rloc = m0 + mi * 16 + (lane >> 2);
#pragma unroll
                for (int nj = 0; nj < 4; nj++) {
                    int cl = n0 + nj * 8 + 2 * (lane & 3);
                    stage[cl * 132 + rloc] = acc[mi][nj][0];
                    stage[(cl + 1) * 132 + rloc] = acc[mi][nj][1];
                    stage[cl * 132 + rloc + 8] = acc[mi][nj][2];
                    stage[(cl + 1) * 132 + rloc + 8] = acc[mi][nj][3];
                }
            }
            __syncthreads();
            for (int rr = 0; rr < 128; rr += 32) {
                int tr = rr + (tid >> 3);
                int off = (tid & 7) * 4;
#pragma unroll
                for (int k = 0; k < 4; k++)
                    *(float4*)(S + (size_t)(cbase + tr) * NT + rbase + off + k * 32) =
                        *(const float4*)(stage + tr * 132 + off + k * 32);
            }
        }
    } else {
        int u = z;
#pragma unroll
        for (int mi = 0; mi < 4; mi++) {
            int row = rbase + m0 + mi * 16 + (lane >> 2);
            ull r0 = ~0ull, r1 = ~0ull;
#pragma unroll
            for (int nj = 0; nj < 4; nj++) {
                int col = cbase + n0 + nj * 8 + 2 * (lane & 3);
                ull k;
                k = packmin(1.f - acc[mi][nj][0], col);     if (k < r0) r0 = k;
                k = packmin(1.f - acc[mi][nj][1], col + 1); if (k < r0) r0 = k;
                k = packmin(1.f - acc[mi][nj][2], col);     if (k < r1) r1 = k;
                k = packmin(1.f - acc[mi][nj][3], col + 1); if (k < r1) r1 = k;
            }
#pragma unroll
            for (int m = 1; m < 4; m <<= 1) {
                ull o0 = __shfl_xor_sync(0xffffffffu, r0, m);
                ull o1 = __shfl_xor_sync(0xffffffffu, r1, m);
                if (o0 < r0) r0 = o0;
                if (o1 < r1) r1 = o1;
            }
            if ((lane & 3) == 0) {
                atomicMin(&g_rowmin[u * NT + row], r0);
                atomicMin(&g_rowmin[u * NT + row + 8], r1);
            }
        }
#pragma unroll
        for (int nj = 0; nj < 4; nj++) {
            int col = cbase + n0 + nj * 8 + 2 * (lane & 3);
            ull c0 = ~0ull, c1 = ~0ull;
#pragma unroll
            for (int mi = 0; mi < 4; mi++) {
                int row = rbase + m0 + mi * 16 + (lane >> 2);
                ull k;
                k = packmin(1.f - acc[mi][nj][0], row);     if (k < c0) c0 = k;
                k = packmin(1.f - acc[mi][nj][2], row + 8); if (k < c0) c0 = k;
                k = packmin(1.f - acc[mi][nj][1], row);     if (k < c1) c1 = k;
                k = packmin(1.f - acc[mi][nj][3], row + 8); if (k < c1) c1 = k;
            }
#pragma unroll
            for (int m = 4; m < 32; m <<= 1) {
                ull o0 = __shfl_xor_sync(0xffffffffu, c0, m);
                ull o1 = __shfl_xor_sync(0xffffffffu, c1, m);
                if (o0 < c0) c0 = o0;
                if (o1 < c1) c1 = o1;
            }
            if ((lane >> 2) == 0) {
                atomicMin(&g_colmin[u * NT + col], c0);
                atomicMin(&g_colmin[u * NT + col + 1], c1);
            }
        }
    }
}

// ---------------------------------------------------------------------------
// Dual-mode self select with float-threshold hot path.
// ---------------------------------------------------------------------------
#define SENTK (((ull)0x7f800000u << 32) | 0xffffffffu)
__global__ void self_select_kernel() {
    __shared__ ull smA[24], smB[24];
    int row = blockIdx.x, s = blockIdx.y;
    int wid = threadIdx.x >> 5, lane = threadIdx.x & 31;
    const float* sqv = g_sq + (size_t)s * NT;
    const float* invv = g_inv + (size_t)s * NT;
    const float* r = g_Sself + (size_t)s * NT * NT + (size_t)row * NT;
    float msq = sqv[row], minv = invv[row];
    ull kA[6], kB[6];
#pragma unroll
    for (int u = 0; u < 6; u++) { kA[u] = SENTK; kB[u] = SENTK; }
    float t5A = INFF, t5B = INFF;

    float4 dd[4], qq[4], ii[4];
#pragma unroll
    for (int it = 0; it < 4; it++) {
        int j0 = wid * 512 + it * 128 + lane * 4;
        dd[it] = *(const float4*)(r + j0);
        qq[it] = *(const float4*)(sqv + j0);
        ii[it] = *(const float4*)(invv + j0);
    }
#pragma unroll
    for (int it = 0; it < 4; it++) {
        int j0 = wid * 512 + it * 128 + lane * 4;
        float d_[4] = {dd[it].x, dd[it].y, dd[it].z, dd[it].w};
        float q_[4] = {qq[it].x, qq[it].y, qq[it].z, qq[it].w};
        float i_[4] = {ii[it].x, ii[it].y, ii[it].z, ii[it].w};
#pragma unroll
        for (int c = 0; c < 4; c++) {
            unsigned j = j0 + c;
            float v0 = fmaxf(msq + q_[c] - 2.f * d_[c], 0.f);
            if (v0 <= t5A) {
                ull k0 = packnn(v0, j);
                if (k0 < kA[5]) {
                    int pos = 5;
                    while (pos > 0 && k0 < kA[pos - 1]) { kA[pos] = kA[pos - 1]; pos--; }
                    kA[pos] = k0;
                    t5A = __uint_as_float((unsigned)(kA[5] >> 32));
                }
            }
            float v1 = fmaxf(1.f - d_[c] * minv * i_[c], 0.f);
            if (v1 <= t5B) {
                ull k1 = packnn(v1, j);
                if (k1 < kB[5]) {
                    int pos = 5;
                    while (pos > 0 && k1 < kB[pos - 1]) { kB[pos] = kB[pos - 1]; pos--; }
                    kB[pos] = k1;
                    t5B = __uint_as_float((unsigned)(kB[5] >> 32));
                }
            }
        }
    }
    for (int t = 0; t < 6; t++) {
        ull m = kA[0];
#pragma unroll
        for (int off = 16; off; off >>= 1) {
            ull o = __shfl_down_sync(0xffffffffu, m, off);
            if (o < m) m = o;
        }
        m = __shfl_sync(0xffffffffu, m, 0);
        if (kA[0] == m) {
#pragma unroll
            for (int u = 0; u < 5; u++) kA[u] = kA[u + 1];
            kA[5] = SENTK;
        }
        if (lane == 0) smA[wid * 6 + t] = m;
        ull w = kB[0];
#pragma unroll
        for (int off = 16; off; off >>= 1) {
            ull o = __shfl_down_sync(0xffffffffu, w, off);
            if (o < w) w = o;
        }
        w = __shfl_sync(0xffffffffu, w, 0);
        if (kB[0] == w) {
#pragma unroll
            for (int u = 0; u < 5; u++) kB[u] = kB[u + 1];
            kB[5] = SENTK;
        }
        if (lane == 0) smB[wid * 6 + t] = w;
    }
    __syncthreads();
    if (wid < 2) {
        ull* sm = wid ? smB : smA;
        int* outp = (wid ? g_neighA : g_neighCB) + (size_t)s * NT * 5 + row * 5;
        ull k = (lane < 24) ? sm[lane] : ~0ull;
        for (int t = 0; t < 6; t++) {
            ull m = k;
#pragma unroll
            for (int off = 16; off; off >>= 1) {
                ull o = __shfl_down_sync(0xffffffffu, m, off);
                if (o < m) m = o;
            }
            m = __shfl_sync(0xffffffffu, m, 0);
            if (k == m) k = ~0ull;
            if (t > 0 && lane == 0) outp[t - 1] = (int)(m & 0xffffffffu);
        }
    }
}

// ---------------------------------------------------------------------------
__global__ void cbneg_kernel(Cfg cfg) {
    __shared__ ull sm[20];
    int row = blockIdx.x, s = blockIdx.y;
    uint32_t k0 = cfg.cbk[s][0], k1 = cfg.cbk[s][1];
    const int* neigh = g_neighCB + (size_t)s * NT * 5;
    int* neg = g_negCB + (size_t)s * NT * 5;
    int wid = threadIdx.x >> 5, lane = threadIdx.x & 31;
    int n0 = neigh[row * 5 + 0], n1 = neigh[row * 5 + 1], n2 = neigh[row * 5 + 2],
        n3 = neigh[row * 5 + 3], n4 = neigh[row * 5 + 4];
    ull kk[5];
#pragma unroll
    for (int u = 0; u < 5; u++) kk[u] = ~0ull;
    int jend = wid * 512 + 512;
    for (int j = wid * 512 + lane; j < jend; j += 32) {
        if (j == row || j == n0 || j == n1 || j == n2 || j == n3 || j == n4) continue;
        uint32_t bits = tf_bits(k0, k1, (uint32_t)(row * NT + j));
        ull k = ((ull)(0x007fffffu - (bits >> 9)) << 32) | (unsigned)j;
        if (k < kk[4]) {
            int pos = 4;
            while (pos > 0 && k < kk[pos - 1]) { kk[pos] = kk[pos - 1]; pos--; }
            kk[pos] = k;
        }
    }
    for (int t = 0; t < 5; t++) {
        ull m = kk[0];
#pragma unroll
        for (int off = 16; off; off >>= 1) {
            ull o = __shfl_down_sync(0xffffffffu, m, off);
            if (o < m) m = o;
        }
        m = __shfl_sync(0xffffffffu, m, 0);
        if (kk[0] == m) {
#pragma unroll
            for (int u = 0; u < 4; u++) kk[u] = kk[u + 1];
            kk[4] = ~0ull;
        }
        if (lane == 0) sm[wid * 5 + t] = m;
    }
    __syncthreads();
    if (wid == 0) {
        ull k = (lane < 20) ? sm[lane] : ~0ull;
        for (int t = 0; t < 5; t++) {
            ull m = k;
#pragma unroll
            for (int off = 16; off; off >>= 1) {
                ull o = __shfl_down_sync(0xffffffffu, m, off);
                if (o < m) m = o;
            }
            m = __shfl_sync(0xffffffffu, m, 0);
            if (k == m) k = ~0ull;
            if (lane == 0) neg[row * 5 + t] = (int)(m & 0xffffffffu);
        }
    }
}

// ---------------------------------------------------------------------------
__global__ void cbloss_kernel(const float* __restrict__ z1n_,
                              const float* __restrict__ z2n_) {
    int s = blockIdx.y;
    int row = (blockIdx.x * blockDim.x + threadIdx.x) >> 5;
    int lane = threadIdx.x & 31;
    if (row >= NT) return;
    const float* An = (s < 4 ? z2n_ : z1n_) + (size_t)(s & 3) * NT * CD;
    const int* neigh = g_neighCB + (size_t)s * NT * 5;
    const int* neg = g_negCB + (size_t)s * NT * 5;
    float a[24];
    const float* ar = An + (size_t)row * CD;
#pragma unroll
    for (int u = 0; u < 24; u++) a[u] = ar[lane + u * 32];
    float sacc = 0.f;
    for (int k = 0; k < 5; k++) {
        const float* pr = An + (size_t)neigh[row * 5 + k] * CD;
        const float* nr = An + (size_t)neg[row * 5 + k] * CD;
        float dp = 0.f, dn = 0.f;
#pragma unroll
        for (int u = 0; u < 24; u++) {
            dp += a[u] * pr[lane + u * 32];
            dn += a[u] * nr[lane + u * 32];
        }
#pragma unroll
        for (int off = 16; off; off >>= 1) {
            dp += __shfl_xor_sync(0xffffffffu, dp, off);
            dn += __shfl_xor_sync(0xffffffffu, dn, off);
        }
        float sp = fminf(fmaxf(dp, -1.f), 1.f);
        float sn = fminf(fmaxf(dn, -1.f), 1.f);
        sacc += fmaxf(sn - sp + 0.05f, 0.f);
    }
    if (lane == 0) g_rowCB[s * NT + row] = sacc;
}

// ---------------------------------------------------------------------------
__global__ void mutual_order_kernel(Cfg cfg) {
    __shared__ int matchs[NT];
    __shared__ int cnt[256];
    __shared__ int excl[257];
    int pi = blockIdx.x;
    int u = cfg.pi_uslot[pi], sw = cfg.pi_swap[pi];
    const ull* rm = (sw ? g_colmin : g_rowmin) + (size_t)u * NT;
    const ull* cm = (sw ? g_rowmin : g_colmin) + (size_t)u * NT;
    int* idxB = g_idxB + (size_t)pi * NT;
    int* order = g_order + (size_t)pi * NT;
    int t = threadIdx.x;
    for (int i = t; i < NT; i += 256) matchs[i] = 0;
    __syncthreads();
    int base = t * 8;
#pragma unroll
    for (int uu = 0; uu < 8; uu++) {
        int i = base + uu;
        int b = (int)(rm[i] & 0xffffffffu);
        int v = ((int)(cm[b] & 0xffffffffu) == i) ? b : -1;
        idxB[i] = v;
        if (v >= 0) matchs[v] = 1;
    }
    __syncthreads();
    int m[8]; int c = 0;
#pragma unroll
    for (int uu = 0; uu < 8; uu++) { m[uu] = matchs[base + uu]; c += (m[uu] == 0); }
    cnt[t] = c;
    __syncthreads();
    if (t == 0) {
        int s = 0;
        for (int i = 0; i < 256; i++) { excl[i] = s; s += cnt[i]; }
        excl[256] = s;
    }
    __syncthreads();
    int Utot = excl[256];
    int uo = excl[t];
    int mm = base - uo;
#pragma unroll
    for (int x = 0; x < 8; x++) {
        if (m[x] == 0) order[uo++] = base + x;
        else           order[Utot + mm++] = base + x;
    }
    if (t == 0) g_negc[pi] = (Utot > 0) ? Utot : 1;
}

// ---------------------------------------------------------------------------
__global__ void nrcloss_kernel(const float* __restrict__ z1n_,
                               const float* __restrict__ z2n_, Cfg cfg) {
    int pi = blockIdx.y;
    int i = (blockIdx.x * blockDim.x + threadIdx.x) >> 5;
    int lane = threadIdx.x & 31;
    if (i >= NT) return;
    int side = cfg.pi_side[pi];
    const float* Bn = (side == 0 ? z2n_ : z1n_) + (size_t)cfg.pi_q[pi] * NT * CD;
    const int* idxB = g_idxB + (size_t)pi * NT;
    const int* neighA = g_neighA + (size_t)(side * 4 + cfg.pi_p[pi]) * NT * 5;
    const int* order = g_order + (size_t)pi * NT;
    uint32_t k0 = cfg.kp[pi][0], k1 = cfg.kp[pi][1];
    int ib = idxB[i];
    int uB = ib < 0 ? 0 : ib;
    int nc = g_negc[pi];
    float a[24];
    const float* ar = Bn + (size_t)uB * CD;
#pragma unroll
    for (int u = 0; u < 24; u++) a[u] = ar[lane + u * 32];
    float hs = 0.f; int npos = 0;
    for (int k = 0; k < 5; k++) {
        int pb = idxB[neighA[i * 5 + k]];
        uint32_t bits = tf_bits(k0, k1, 10240u + (uint32_t)(i * 5 + k));
        int nb = order[(int)(bits & 2047u) % nc];
        const float* pr = Bn + (size_t)(pb < 0 ? 0 : pb) * CD;
        const float* nr = Bn + (size_t)nb * CD;
        float dp = 0.f, dn = 0.f;
#pragma unroll
        for (int u = 0; u < 24; u++) {
            dp += a[u] * pr[lane + u * 32];
            dn += a[u] * nr[lane + u * 32];
        }
#pragma unroll
        for (int off = 16; off; off >>= 1) {
            dp += __shfl_xor_sync(0xffffffffu, dp, off);
            dn += __shfl_xor_sync(0xffffffffu, dn, off);
        }
        if (pb >= 0) { hs += fmaxf(dn - dp + 0.4f, 0.f); npos++; }
    }
    if (lane == 0) {
        float per = hs / (float)(npos > 0 ? npos : 1);
        int valid = (ib >= 0) && (npos > 0);
        g_rowNRC[pi * NT + i] = valid ? per : 0.f;
        g_cntNRC[pi * NT + i] = valid ? 1.f : 0.f;
    }
}

// ---------------------------------------------------------------------------
__global__ void reduce_all_kernel() {
    __shared__ float sh[1024];
    int slot = blockIdx.x;
    int t = threadIdx.x;
    const float* buf;
    if (slot < 8) buf = g_rowCB + (size_t)slot * NT;
    else if (slot < 20) buf = g_rowNRC + (size_t)(slot - 8) * NT;
    else buf = g_cntNRC + (size_t)(slot - 20) * NT;
    sh[t] = buf[t] + buf[t + 1024];
    __syncthreads();
    for (int s = 512; s; s >>= 1) {
        if (t < s) sh[t] += sh[t + s];
        __syncthreads();
    }
    if (t == 0) {
        float v = sh[0];
        if (slot < 8) v *= (1.0f / 10240.0f);
        g_slots[slot] = v;
    }
}

__global__ void final_kernel(float* __restrict__ out) {
    float l2 = 0.f;
    for (int i = 0; i < 8; i++) l2 += g_slots[i];
    l2 *= 0.25f;
    float l3 = 0.f;
    for (int s = 0; s < 2; s++) {
        float acc = 0.f;
        for (int j = 0; j < 6; j++) {
            int pi = s * 6 + j;
            float cn = g_slots[20 + pi];
            float sm = g_slots[8 + pi];
            acc += (cn > 0.f) ? sm / fmaxf(cn, 1.f) : 0.f;
        }
        l3 += acc / 6.f;
    }
    out[0] = 10.f * l2 + 10.f * l3;
}

// ---------------------------------------------------------------------------
namespace {
struct HostMT { uint32_t mt[624]; int pos; };
static void mt_seed(HostMT& s, uint32_t seed) {
    for (int p = 0; p < 624; p++) {
        s.mt[p] = seed;
        seed = 1812433253u * (seed ^ (seed >> 30)) + (uint32_t)p + 1u;
    }
    s.pos = 624;
}
static uint32_t mt_next(HostMT& s) {
    if (s.pos == 624) {
        for (int i = 0; i < 624; i++) {
            uint32_t y = (s.mt[i] & 0x80000000u) | (s.mt[(i + 1) % 624] & 0x7fffffffu);
            s.mt[i] = s.mt[(i + 397) % 624] ^ (y >> 1) ^ ((y & 1u) ? 0x9908b0dfu : 0u);
        }
        s.pos = 0;
    }
    uint32_t y = s.mt[s.pos++];
    y ^= y >> 11;
    y ^= (y << 7) & 0x9d2c5680u;
    y ^= (y << 15) & 0xefc60000u;
    y ^= y >> 18;
    return y;
}
static uint32_t mt_interval(HostMT& s, uint32_t mx) {
    if (mx == 0) return 0;
    uint32_t mask = mx;
    mask |= mask >> 1; mask |= mask >> 2; mask |= mask >> 4;
    mask |= mask >> 8; mask |= mask >> 16;
    uint32_t v;
    while ((v = (mt_next(s) & mask)) > mx) {}
    return v;
}
static void perm12(uint32_t seed, int* out) {
    HostMT s; mt_seed(s, seed);
    for (int i = 0; i < 12; i++) out[i] = i;
    for (int i = 11; i > 0; i--) {
        int j = (int)mt_interval(s, (uint32_t)i);
        int t = out[i]; out[i] = out[j]; out[j] = t;
    }
}
}  // namespace

// ---------------------------------------------------------------------------
extern "C" void kernel_launch(void* const* d_in, const int* in_sizes, int n_in,
                              void* d_out, int out_size) {
    const float* z1 = (const float*)d_in[0];
    const float* z2 = (const float*)d_in[1];
    float* out = (float*)d_out;

    float *z1n, *z2n;
    __nv_bfloat16 *rh, *rl, *nh, *nl;
    cudaGetSymbolAddress((void**)&z1n, g_z1n);
    cudaGetSymbolAddress((void**)&z2n, g_z2n);
    cudaGetSymbolAddress((void**)&rh, g_rh);
    cudaGetSymbolAddress((void**)&rl, g_rl);
    cudaGetSymbolAddress((void**)&nh, g_nh);
    cudaGetSymbolAddress((void**)&nl, g_nl);

    Cfg cfg;
    uint32_t ck[4][2];
    for (int i = 0; i < 4; i++)
        threefry2x32(0u, 42u, 0u, (uint32_t)i, ck[i][0], ck[i][1]);
    for (int b = 0; b < 4; b++) {
        threefry2x32(ck[0][0], ck[0][1], 0u, (uint32_t)b, cfg.cbk[b][0], cfg.cbk[b][1]);
        threefry2x32(ck[1][0], ck[1][1], 0u, (uint32_t)b, cfg.cbk[4 + b][0], cfg.cbk[4 + b][1]);
    }
    for (int j = 0; j < 6; j++) {
        threefry2x32(ck[2][0], ck[2][1], 0u, (uint32_t)j, cfg.kp[j][0], cfg.kp[j][1]);
        threefry2x32(ck[3][0], ck[3][1], 0u, (uint32_t)j, cfg.kp[6 + j][0], cfg.kp[6 + j][1]);
    }

    int allp[12][2];
    { int t = 0;
      for (int p = 0; p < 4; p++)
          for (int q = 0; q < 4; q++)
              if (p != q) { allp[t][0] = p; allp[t][1] = q; t++; } }
    int pairs[12][2];
    int perm[12];
    perm12(0u, perm);
    for (int j = 0; j < 6; j++) { pairs[j][0] = allp[perm[j]][0]; pairs[j][1] = allp[perm[j]][1]; }
    perm12(1u, perm);
    for (int j = 0; j < 6; j++) { pairs[6 + j][0] = allp[perm[j]][0]; pairs[6 + j][1] = allp[perm[j]][1]; }

    for (int pi = 0; pi < 12; pi++) {
        cfg.pi_side[pi] = pi / 6;
        cfg.pi_p[pi] = pairs[pi][0];
        cfg.pi_q[pi] = pairs[pi][1];
    }
    int nU = 0;
    bool matched1[12] = {false};
    for (int j0 = 0; j0 < 6; j0++) {
        cfg.u_side[nU] = 0; cfg.u_p[nU] = pairs[j0][0]; cfg.u_q[nU] = pairs[j0][1];
        cfg.pi_uslot[j0] = nU; cfg.pi_swap[j0] = 0;
        for (int j1 = 6; j1 < 12; j1++) {
            if (!matched1[j1] && pairs[j1][0] == pairs[j0][1] && pairs[j1][1] == pairs[j0][0]) {
                cfg.pi_uslot[j1] = nU; cfg.pi_swap[j1] = 1;
                matched1[j1] = true;
                break;
            }
        }
        nU++;
    }
    for (int j1 = 6; j1 < 12; j1++) {
        if (!matched1[j1]) {
            cfg.u_side[nU] = 1; cfg.u_p[nU] = pairs[j1][0]; cfg.u_q[nU] = pairs[j1][1];
            cfg.pi_uslot[j1] = nU; cfg.pi_swap[j1] = 0;
            nU++;
        }
    }
    cfg.nU = nU;

    static cudaStream_t s1 = nullptr;
    static cudaEvent_t evS = nullptr, evJ = nullptr;
    static bool attrSet = false;
    if (!attrSet) {
        cudaFuncSetAttribute(mma_gemm_kernel,
                             cudaFuncAttributeMaxDynamicSharedMemorySize, 2 * STG);
        cudaStreamCreateWithFlags(&s1, cudaStreamNonBlocking);
        cudaEventCreateWithFlags(&evS, cudaEventDisableTiming);
        cudaEventCreateWithFlags(&evJ, cudaEventDisableTiming);
        attrSet = true;
    }

    // Stream 0: normalize + init + self GEMM, then fork AFTER self GEMM so the
    // cross GEMM (tensor-bound) overlaps the select chain (ALU/latency-bound).
    normalize_kernel<<<2048, 256>>>(z1, z2);
    init_kernel<<<48, 1024>>>();
    mma_gemm_kernel<<<dim3(16, 16, 8), 256, 2 * STG>>>(rh, rl, nh, nl, 0, cfg);
    cudaEventRecord(evS, 0);
    cudaStreamWaitEvent(s1, evS, 0);

    // Branch 1 (s1): cross GEMM + fused argmin -> mutual matching.
    mma_gemm_kernel<<<dim3(16, 16, nU), 256, 2 * STG, s1>>>(rh, rl, nh, nl, 1, cfg);
    mutual_order_kernel<<<12, 256, 0, s1>>>(cfg);
    cudaEventRecord(evJ, s1);

    // Branch 0: select -> crossbrain chain (overlaps branch 1).
    self_select_kernel<<<dim3(NT, 8), 128>>>();
    cbneg_kernel<<<dim3(NT, 8), 128>>>(cfg);
    cbloss_kernel<<<dim3(256, 8), 256>>>(z1n, z2n);

    // Join, then NRC losses + reductions.
    cudaStreamWaitEvent(0, evJ, 0);
    nrcloss_kernel<<<dim3(256, 12), 256>>>(z1n, z2n, cfg);
    reduce_all_kernel<<<32, 1024>>>();
    final_kernel<<<1, 1>>>(out);
}